// round 1
// baseline (speedup 1.0000x reference)
#include <cuda_runtime.h>
#include <cstdint>

#define TOTAL 6464
#define CDIM  256
#define HEADS 8
#define HD    32
#define BATCH 8

// Scratch (static __device__ arrays — allowed; no runtime allocation)
__device__ float g_qkv[TOTAL * 768];   // [token][3*256]: Q cols 0..255, K 256..511, V 512..767
__device__ float g_att[TOTAL * CDIM];  // attention output, head-major per token
__device__ int   g_off[BATCH + 1];

// ---------------------------------------------------------------------------
// Prefix-sum of batch lengths (tiny, deterministic, capturable)
// ---------------------------------------------------------------------------
__global__ void offsets_kernel(const int* __restrict__ lens) {
    if (threadIdx.x == 0 && blockIdx.x == 0) {
        int s = 0;
        for (int i = 0; i < BATCH; i++) { g_off[i] = s; s += lens[i]; }
        g_off[BATCH] = s;
    }
}

// ---------------------------------------------------------------------------
// C[M,N] = A[M,K] @ B[K,N] + bias[N]
// Requires M%64==0, N%64==0, K%16==0 (true for all uses here).
// Block 256 threads, 64x64 tile, BK=16, 4x4 register micro-tile.
// ---------------------------------------------------------------------------
__global__ __launch_bounds__(256) void sgemm_bias(
    const float* __restrict__ A, const float* __restrict__ B,
    const float* __restrict__ bias, float* __restrict__ C,
    int M, int N, int K)
{
    __shared__ float As[16][68];   // transposed: As[k][m]
    __shared__ float Bs[16][68];   // Bs[k][n]

    const int tid = threadIdx.x;
    const int tx = tid & 15, ty = tid >> 4;
    const int row0 = blockIdx.y * 64, col0 = blockIdx.x * 64;

    const int lm  = tid >> 2, lks = tid & 3;   // A: row lm, k-slot lks
    const int lkb = tid >> 4, lc  = tid & 15;  // B: k-row lkb, col-slot lc

    float acc[4][4] = {};

    for (int kk = 0; kk < K; kk += 16) {
        float4 a4 = *(const float4*)&A[(size_t)(row0 + lm) * K + kk + lks * 4];
        As[lks * 4 + 0][lm] = a4.x;
        As[lks * 4 + 1][lm] = a4.y;
        As[lks * 4 + 2][lm] = a4.z;
        As[lks * 4 + 3][lm] = a4.w;
        *(float4*)&Bs[lkb][lc * 4] =
            *(const float4*)&B[(size_t)(kk + lkb) * N + col0 + lc * 4];
        __syncthreads();

        #pragma unroll
        for (int k = 0; k < 16; k++) {
            float4 av = *(const float4*)&As[k][ty * 4];
            float4 bv = *(const float4*)&Bs[k][tx * 4];
            float a_[4] = {av.x, av.y, av.z, av.w};
            float b_[4] = {bv.x, bv.y, bv.z, bv.w};
            #pragma unroll
            for (int i = 0; i < 4; i++)
                #pragma unroll
                for (int j = 0; j < 4; j++)
                    acc[i][j] += a_[i] * b_[j];
        }
        __syncthreads();
    }

    float4 bv = *(const float4*)&bias[col0 + tx * 4];
    #pragma unroll
    for (int i = 0; i < 4; i++) {
        float4 o;
        o.x = acc[i][0] + bv.x;
        o.y = acc[i][1] + bv.y;
        o.z = acc[i][2] + bv.z;
        o.w = acc[i][3] + bv.w;
        *(float4*)&C[(size_t)(row0 + ty * 4 + i) * N + col0 + tx * 4] = o;
    }
}

// ---------------------------------------------------------------------------
// Ragged flash attention. One lane per query row; q and o live in registers;
// softmax state is lane-local (no shuffles). Block = 128 threads = 4 warps =
// 128 queries. K/V staged to smem in 64-key chunks; all compute reads are
// warp-uniform broadcasts (conflict-free).
// grid = (8 q-tiles, 8 heads, 8 batches)
// ---------------------------------------------------------------------------
__global__ __launch_bounds__(128) void attn_kernel(const int* __restrict__ lens)
{
    const int qt = blockIdx.x, h = blockIdx.y, b = blockIdx.z;
    const int L = lens[b];
    const int q0 = qt * 128;
    if (q0 >= L) return;
    const int off = g_off[b];

    __shared__ float Ks[64 * 32];
    __shared__ float Vs[64 * 32];

    const int tid = threadIdx.x, lane = tid & 31, wid = tid >> 5;
    const float scale = 0.17677669529663687f;  // 32^-0.5

    const int q = q0 + wid * 32 + lane;

    float4 qr[8];
    if (q < L) {
        const float4* qp = (const float4*)(g_qkv + (size_t)(off + q) * 768 + h * HD);
        #pragma unroll
        for (int d = 0; d < 8; d++) {
            float4 t = qp[d];
            t.x *= scale; t.y *= scale; t.z *= scale; t.w *= scale;
            qr[d] = t;
        }
    } else {
        #pragma unroll
        for (int d = 0; d < 8; d++) qr[d] = make_float4(0.f, 0.f, 0.f, 0.f);
    }

    float4 o[8];
    #pragma unroll
    for (int d = 0; d < 8; d++) o[d] = make_float4(0.f, 0.f, 0.f, 0.f);
    float m = -1e30f, lsum = 0.f;

    for (int k0 = 0; k0 < L; k0 += 64) {
        __syncthreads();   // protect smem reuse from previous chunk
        // Stage K,V chunk: 64 keys x 32 dims each; 8 float4 per thread total.
        #pragma unroll
        for (int i = 0; i < 4; i++) {
            int idx = tid + i * 128;          // 0..511 float4 slots
            int key = idx >> 3, sl = idx & 7;
            int gk = k0 + key;
            float4 kv = make_float4(0.f, 0.f, 0.f, 0.f);
            float4 vv = kv;
            if (gk < L) {
                const float* base = g_qkv + (size_t)(off + gk) * 768 + h * HD + sl * 4;
                kv = *(const float4*)(base + 256);
                vv = *(const float4*)(base + 512);
            }
            *(float4*)&Ks[idx * 4] = kv;
            *(float4*)&Vs[idx * 4] = vv;
        }
        __syncthreads();

        const int nk = min(64, L - k0);
        for (int j0 = 0; j0 < nk; j0 += 16) {
            float s[16];
            #pragma unroll
            for (int jj = 0; jj < 16; jj++) {
                const float4* kr = (const float4*)&Ks[(j0 + jj) * 32];
                float acc = 0.f;
                #pragma unroll
                for (int d = 0; d < 8; d++) {
                    float4 k4 = kr[d];
                    acc += qr[d].x * k4.x + qr[d].y * k4.y
                         + qr[d].z * k4.z + qr[d].w * k4.w;
                }
                s[jj] = (j0 + jj < nk) ? acc : -1e30f;
            }
            // lane-local online softmax
            float mc = s[0];
            #pragma unroll
            for (int jj = 1; jj < 16; jj++) mc = fmaxf(mc, s[jj]);
            float mn = fmaxf(m, mc);
            float corr = __expf(m - mn);
            m = mn;
            float psum = 0.f;
            #pragma unroll
            for (int jj = 0; jj < 16; jj++) { s[jj] = __expf(s[jj] - mn); psum += s[jj]; }
            lsum = lsum * corr + psum;
            #pragma unroll
            for (int d = 0; d < 8; d++) {
                o[d].x *= corr; o[d].y *= corr; o[d].z *= corr; o[d].w *= corr;
            }
            #pragma unroll
            for (int jj = 0; jj < 16; jj++) {
                const float4* vr = (const float4*)&Vs[(j0 + jj) * 32];
                float p = s[jj];
                #pragma unroll
                for (int d = 0; d < 8; d++) {
                    float4 v4 = vr[d];
                    o[d].x += p * v4.x; o[d].y += p * v4.y;
                    o[d].z += p * v4.z; o[d].w += p * v4.w;
                }
            }
        }
    }

    if (q < L) {
        float inv = 1.f / lsum;
        float4* dst = (float4*)(g_att + (size_t)(off + q) * CDIM + h * HD);
        #pragma unroll
        for (int d = 0; d < 8; d++) {
            float4 t = o[d];
            t.x *= inv; t.y *= inv; t.z *= inv; t.w *= inv;
            dst[d] = t;
        }
    }
}

// ---------------------------------------------------------------------------
// Launch: offsets -> QKV gemm -> ragged attention -> proj gemm
// inputs: 0 carrier_tokens [6464,256] f32, 1 ct_mask (unused), 2 lens int32[8],
//         3 qkv_w [256,768], 4 qkv_b [768], 5 proj_w [256,256], 6 proj_b [256]
// ---------------------------------------------------------------------------
extern "C" void kernel_launch(void* const* d_in, const int* in_sizes, int n_in,
                              void* d_out, int out_size)
{
    const float* x      = (const float*)d_in[0];
    const int*   lens   = (const int*)d_in[2];
    const float* qkv_w  = (const float*)d_in[3];
    const float* qkv_b  = (const float*)d_in[4];
    const float* proj_w = (const float*)d_in[5];
    const float* proj_b = (const float*)d_in[6];
    float* out = (float*)d_out;

    float *qkv_p = nullptr, *att_p = nullptr;
    cudaGetSymbolAddress((void**)&qkv_p, g_qkv);
    cudaGetSymbolAddress((void**)&att_p, g_att);

    offsets_kernel<<<1, 1>>>(lens);
    sgemm_bias<<<dim3(768 / 64, TOTAL / 64), 256>>>(x, qkv_w, qkv_b, qkv_p,
                                                    TOTAL, 768, 256);
    attn_kernel<<<dim3(8, HEADS, BATCH), 128>>>(lens);
    sgemm_bias<<<dim3(256 / 64, TOTAL / 64), 256>>>(att_p, proj_w, proj_b, out,
                                                    TOTAL, 256, 256);
}

// round 2
// speedup vs baseline: 2.1482x; 2.1482x over previous
#include <cuda_runtime.h>
#include <cuda_bf16.h>
#include <cstdint>

#define TOTAL 6464
#define CDIM  256
#define HEADS 8
#define HD    32
#define BATCH 8

// Scratch (static __device__ arrays — no runtime allocation)
__device__ float g_qkv[TOTAL * 768];   // [token][3*256]: Q 0..255, K 256..511, V 512..767
__device__ float g_att[TOTAL * CDIM];  // attention output
__device__ int   g_off[BATCH + 1];

// ---------------------------------------------------------------------------
__global__ void offsets_kernel(const int* __restrict__ lens) {
    if (threadIdx.x == 0 && blockIdx.x == 0) {
        int s = 0;
        for (int i = 0; i < BATCH; i++) { g_off[i] = s; s += lens[i]; }
        g_off[BATCH] = s;
    }
}

// ---------------------------------------------------------------------------
// helpers
// ---------------------------------------------------------------------------
__device__ __forceinline__ uint32_t cvt_tf32(float f) {
    uint32_t u; asm("cvt.rna.tf32.f32 %0, %1;" : "=r"(u) : "f"(f)); return u;
}
__device__ __forceinline__ uint32_t packbf(float x, float y) {
    __nv_bfloat162 t = __floats2bfloat162_rn(x, y);
    return reinterpret_cast<uint32_t&>(t);
}
__device__ __forceinline__ float bfhi(float x) {
    return __bfloat162float(__float2bfloat16(x));
}
__device__ __forceinline__ void mma_tf32(float* c, uint32_t a0, uint32_t a1,
                                         uint32_t a2, uint32_t a3,
                                         uint32_t b0, uint32_t b1) {
    asm("mma.sync.aligned.m16n8k8.row.col.f32.tf32.tf32.f32 "
        "{%0,%1,%2,%3},{%4,%5,%6,%7},{%8,%9},{%0,%1,%2,%3};"
        : "+f"(c[0]), "+f"(c[1]), "+f"(c[2]), "+f"(c[3])
        : "r"(a0), "r"(a1), "r"(a2), "r"(a3), "r"(b0), "r"(b1));
}
__device__ __forceinline__ void mma_bf16(float* c, const uint32_t* a, const uint32_t* b) {
    asm("mma.sync.aligned.m16n8k16.row.col.f32.bf16.bf16.f32 "
        "{%0,%1,%2,%3},{%4,%5,%6,%7},{%8,%9},{%0,%1,%2,%3};"
        : "+f"(c[0]), "+f"(c[1]), "+f"(c[2]), "+f"(c[3])
        : "r"(a[0]), "r"(a[1]), "r"(a[2]), "r"(a[3]), "r"(b[0]), "r"(b[1]));
}

// ---------------------------------------------------------------------------
// C[M,N] = A[M,K] @ B[K,N] + bias, fp32 in/out, bf16-split tensor-core compute
// (3-pass: ah*bh + ah*bl + al*bh -> ~1e-5 rel err).
// Requires M%64==0, N%64==0, K%16==0. Block 128 thr (4 warps, 2x2), tile 64x64.
// ---------------------------------------------------------------------------
__global__ __launch_bounds__(128) void gemm_bf16x2(
    const float* __restrict__ A, const float* __restrict__ B,
    const float* __restrict__ bias, float* __restrict__ C,
    int M, int N, int K)
{
    __shared__ uint32_t Ah[64][9], Al[64][9];   // [m][k-pair] (k=2j, 2j+1)
    __shared__ uint32_t Bh[64][9], Bl[64][9];   // [n][k-pair]

    const int tid = threadIdx.x, lane = tid & 31, wid = tid >> 5;
    const int g = lane >> 2, tig = lane & 3;
    const int wm = wid >> 1, wn = wid & 1;
    const int row0 = blockIdx.y * 64, col0 = blockIdx.x * 64;
    const int m0 = wm * 32, n0 = wn * 32;

    float c[2][4][4];
    #pragma unroll
    for (int mt = 0; mt < 2; mt++)
        #pragma unroll
        for (int nt = 0; nt < 4; nt++)
            #pragma unroll
            for (int i = 0; i < 4; i++) c[mt][nt][i] = 0.f;

    for (int kk = 0; kk < K; kk += 16) {
        __syncthreads();
        // stage A: 64 rows x 16 k = 256 float4, 2 per thread
        #pragma unroll
        for (int i = 0; i < 2; i++) {
            int idx = tid + i * 128;
            int am = idx >> 2, as = idx & 3;
            float4 v = *(const float4*)&A[(size_t)(row0 + am) * K + kk + as * 4];
            float hx = bfhi(v.x), hy = bfhi(v.y), hz = bfhi(v.z), hw = bfhi(v.w);
            Ah[am][as * 2 + 0] = packbf(v.x, v.y);
            Ah[am][as * 2 + 1] = packbf(v.z, v.w);
            Al[am][as * 2 + 0] = packbf(v.x - hx, v.y - hy);
            Al[am][as * 2 + 1] = packbf(v.z - hz, v.w - hw);
        }
        // stage B: thread covers 2 adjacent k-rows x 4 n
        {
            int ns = tid & 15, kp = tid >> 4;   // kp 0..7
            const float* Bp = &B[(size_t)(kk + 2 * kp) * N + col0 + ns * 4];
            float4 r0 = *(const float4*)Bp;
            float4 r1 = *(const float4*)(Bp + N);
            float h0x = bfhi(r0.x), h0y = bfhi(r0.y), h0z = bfhi(r0.z), h0w = bfhi(r0.w);
            float h1x = bfhi(r1.x), h1y = bfhi(r1.y), h1z = bfhi(r1.z), h1w = bfhi(r1.w);
            Bh[ns * 4 + 0][kp] = packbf(r0.x, r1.x);
            Bh[ns * 4 + 1][kp] = packbf(r0.y, r1.y);
            Bh[ns * 4 + 2][kp] = packbf(r0.z, r1.z);
            Bh[ns * 4 + 3][kp] = packbf(r0.w, r1.w);
            Bl[ns * 4 + 0][kp] = packbf(r0.x - h0x, r1.x - h1x);
            Bl[ns * 4 + 1][kp] = packbf(r0.y - h0y, r1.y - h1y);
            Bl[ns * 4 + 2][kp] = packbf(r0.z - h0z, r1.z - h1z);
            Bl[ns * 4 + 3][kp] = packbf(r0.w - h0w, r1.w - h1w);
        }
        __syncthreads();

        uint32_t ah[2][4], al[2][4], bh[4][2], bl[4][2];
        #pragma unroll
        for (int mt = 0; mt < 2; mt++) {
            int r = m0 + mt * 16;
            ah[mt][0] = Ah[r + g][tig];     ah[mt][1] = Ah[r + g + 8][tig];
            ah[mt][2] = Ah[r + g][tig + 4]; ah[mt][3] = Ah[r + g + 8][tig + 4];
            al[mt][0] = Al[r + g][tig];     al[mt][1] = Al[r + g + 8][tig];
            al[mt][2] = Al[r + g][tig + 4]; al[mt][3] = Al[r + g + 8][tig + 4];
        }
        #pragma unroll
        for (int nt = 0; nt < 4; nt++) {
            int n = n0 + nt * 8 + g;
            bh[nt][0] = Bh[n][tig]; bh[nt][1] = Bh[n][tig + 4];
            bl[nt][0] = Bl[n][tig]; bl[nt][1] = Bl[n][tig + 4];
        }
        #pragma unroll
        for (int mt = 0; mt < 2; mt++)
            #pragma unroll
            for (int nt = 0; nt < 4; nt++) {
                mma_bf16(c[mt][nt], ah[mt], bh[nt]);
                mma_bf16(c[mt][nt], ah[mt], bl[nt]);
                mma_bf16(c[mt][nt], al[mt], bh[nt]);
            }
    }

    #pragma unroll
    for (int mt = 0; mt < 2; mt++)
        #pragma unroll
        for (int nt = 0; nt < 4; nt++) {
            int r = row0 + m0 + mt * 16 + g;
            int cc = col0 + n0 + nt * 8 + 2 * tig;
            float2 bv = *(const float2*)&bias[cc];
            float2 o0 = {c[mt][nt][0] + bv.x, c[mt][nt][1] + bv.y};
            float2 o1 = {c[mt][nt][2] + bv.x, c[mt][nt][3] + bv.y};
            *(float2*)&C[(size_t)r * N + cc] = o0;
            *(float2*)&C[(size_t)(r + 8) * N + cc] = o1;
        }
}

// ---------------------------------------------------------------------------
// Ragged flash attention, tf32 tensor cores.
// Block 128 thr = 4 warps; each warp owns 16 queries (m16). Q-tile 64,
// K-chunks of 64. S = Q@K^T via m16n8k8 tf32; P routed through smem; P@V via
// m16n8k8 tf32. Online softmax with quad-shfl row reductions.
// grid = (16 q-tiles, 8 heads, 8 batches)
// ---------------------------------------------------------------------------
__global__ __launch_bounds__(128) void attn_tf32(const int* __restrict__ lens)
{
    const int qt = blockIdx.x, h = blockIdx.y, b = blockIdx.z;
    const int L = lens[b];
    const int q0 = qt * 64;
    if (q0 >= L) return;
    const int off = g_off[b];

    __shared__ uint32_t Qs[64][36];  // [query][dim]   (4g+tig perm -> conflict-free)
    __shared__ uint32_t Ks[64][36];  // [key][dim]
    __shared__ uint32_t Vs[64][36];  // [key][dim]
    __shared__ uint32_t Ps[64][68];  // [query][key]

    const int tid = threadIdx.x, lane = tid & 31, wid = tid >> 5;
    const int g = lane >> 2, tig = lane & 3;
    const int m0 = wid * 16;
    const float sc = 0.17677669529663687f;  // 32^-0.5

    // stage Q (scaled, tf32), zero-padded rows
    #pragma unroll
    for (int i = 0; i < 4; i++) {
        int idx = tid + i * 128;
        int r = idx >> 3, s = idx & 7;
        float4 v = make_float4(0.f, 0.f, 0.f, 0.f);
        if (q0 + r < L)
            v = *(const float4*)&g_qkv[(size_t)(off + q0 + r) * 768 + h * HD + s * 4];
        Qs[r][s * 4 + 0] = cvt_tf32(v.x * sc);
        Qs[r][s * 4 + 1] = cvt_tf32(v.y * sc);
        Qs[r][s * 4 + 2] = cvt_tf32(v.z * sc);
        Qs[r][s * 4 + 3] = cvt_tf32(v.w * sc);
    }

    float o[4][4];
    #pragma unroll
    for (int nt = 0; nt < 4; nt++)
        #pragma unroll
        for (int i = 0; i < 4; i++) o[nt][i] = 0.f;
    float mrow0 = -1e30f, mrow1 = -1e30f, l0 = 0.f, l1 = 0.f;

    for (int k0 = 0; k0 < L; k0 += 64) {
        __syncthreads();
        #pragma unroll
        for (int i = 0; i < 4; i++) {
            int idx = tid + i * 128;
            int r = idx >> 3, s = idx & 7;
            float4 kv = make_float4(0.f, 0.f, 0.f, 0.f), vv = kv;
            if (k0 + r < L) {
                const float* p = &g_qkv[(size_t)(off + k0 + r) * 768 + h * HD + s * 4];
                kv = *(const float4*)(p + 256);
                vv = *(const float4*)(p + 512);
            }
            Ks[r][s * 4 + 0] = cvt_tf32(kv.x); Ks[r][s * 4 + 1] = cvt_tf32(kv.y);
            Ks[r][s * 4 + 2] = cvt_tf32(kv.z); Ks[r][s * 4 + 3] = cvt_tf32(kv.w);
            Vs[r][s * 4 + 0] = cvt_tf32(vv.x); Vs[r][s * 4 + 1] = cvt_tf32(vv.y);
            Vs[r][s * 4 + 2] = cvt_tf32(vv.z); Vs[r][s * 4 + 3] = cvt_tf32(vv.w);
        }
        __syncthreads();

        // S = Q @ K^T : 8 key-tiles x 4 k-steps
        float s_[8][4] = {};
        #pragma unroll
        for (int ks = 0; ks < 4; ks++) {
            uint32_t a0 = Qs[m0 + g][ks * 8 + tig];
            uint32_t a1 = Qs[m0 + g + 8][ks * 8 + tig];
            uint32_t a2 = Qs[m0 + g][ks * 8 + tig + 4];
            uint32_t a3 = Qs[m0 + g + 8][ks * 8 + tig + 4];
            #pragma unroll
            for (int jt = 0; jt < 8; jt++) {
                uint32_t b0 = Ks[jt * 8 + g][ks * 8 + tig];
                uint32_t b1 = Ks[jt * 8 + g][ks * 8 + tig + 4];
                mma_tf32(s_[jt], a0, a1, a2, a3, b0, b1);
            }
        }
        // ragged key mask (only in last partial chunk)
        if (k0 + 64 > L) {
            #pragma unroll
            for (int jt = 0; jt < 8; jt++) {
                int col = k0 + jt * 8 + 2 * tig;
                if (col >= L)     { s_[jt][0] = -1e9f; s_[jt][2] = -1e9f; }
                if (col + 1 >= L) { s_[jt][1] = -1e9f; s_[jt][3] = -1e9f; }
            }
        }
        // online softmax (rows g and g+8)
        float mx0 = -1e30f, mx1 = -1e30f;
        #pragma unroll
        for (int jt = 0; jt < 8; jt++) {
            mx0 = fmaxf(mx0, fmaxf(s_[jt][0], s_[jt][1]));
            mx1 = fmaxf(mx1, fmaxf(s_[jt][2], s_[jt][3]));
        }
        mx0 = fmaxf(mx0, __shfl_xor_sync(0xffffffffu, mx0, 1));
        mx0 = fmaxf(mx0, __shfl_xor_sync(0xffffffffu, mx0, 2));
        mx1 = fmaxf(mx1, __shfl_xor_sync(0xffffffffu, mx1, 1));
        mx1 = fmaxf(mx1, __shfl_xor_sync(0xffffffffu, mx1, 2));
        float mn0 = fmaxf(mrow0, mx0), mn1 = fmaxf(mrow1, mx1);
        float cr0 = __expf(mrow0 - mn0), cr1 = __expf(mrow1 - mn1);
        mrow0 = mn0; mrow1 = mn1;
        float ps0 = 0.f, ps1 = 0.f;
        #pragma unroll
        for (int jt = 0; jt < 8; jt++) {
            s_[jt][0] = __expf(s_[jt][0] - mn0); ps0 += s_[jt][0];
            s_[jt][1] = __expf(s_[jt][1] - mn0); ps0 += s_[jt][1];
            s_[jt][2] = __expf(s_[jt][2] - mn1); ps1 += s_[jt][2];
            s_[jt][3] = __expf(s_[jt][3] - mn1); ps1 += s_[jt][3];
        }
        l0 = l0 * cr0 + ps0;
        l1 = l1 * cr1 + ps1;
        #pragma unroll
        for (int nt = 0; nt < 4; nt++) {
            o[nt][0] *= cr0; o[nt][1] *= cr0;
            o[nt][2] *= cr1; o[nt][3] *= cr1;
        }
        // P -> smem (tf32), warp-private rows
        #pragma unroll
        for (int jt = 0; jt < 8; jt++) {
            uint2 p01 = {cvt_tf32(s_[jt][0]), cvt_tf32(s_[jt][1])};
            uint2 p23 = {cvt_tf32(s_[jt][2]), cvt_tf32(s_[jt][3])};
            *(uint2*)&Ps[m0 + g][jt * 8 + 2 * tig] = p01;
            *(uint2*)&Ps[m0 + g + 8][jt * 8 + 2 * tig] = p23;
        }
        __syncwarp();
        // O += P @ V : 8 k-steps (keys) x 4 n-tiles (dims)
        #pragma unroll
        for (int ks = 0; ks < 8; ks++) {
            uint32_t a0 = Ps[m0 + g][ks * 8 + tig];
            uint32_t a1 = Ps[m0 + g + 8][ks * 8 + tig];
            uint32_t a2 = Ps[m0 + g][ks * 8 + tig + 4];
            uint32_t a3 = Ps[m0 + g + 8][ks * 8 + tig + 4];
            #pragma unroll
            for (int nt = 0; nt < 4; nt++) {
                uint32_t b0 = Vs[ks * 8 + tig][nt * 8 + g];
                uint32_t b1 = Vs[ks * 8 + tig + 4][nt * 8 + g];
                mma_tf32(o[nt], a0, a1, a2, a3, b0, b1);
            }
        }
    }

    l0 += __shfl_xor_sync(0xffffffffu, l0, 1);
    l0 += __shfl_xor_sync(0xffffffffu, l0, 2);
    l1 += __shfl_xor_sync(0xffffffffu, l1, 1);
    l1 += __shfl_xor_sync(0xffffffffu, l1, 2);
    float i0 = 1.f / l0, i1 = 1.f / l1;

    int qa = q0 + m0 + g, qb = qa + 8;
    #pragma unroll
    for (int nt = 0; nt < 4; nt++) {
        int cc = h * HD + nt * 8 + 2 * tig;
        if (qa < L) {
            float2 v = {o[nt][0] * i0, o[nt][1] * i0};
            *(float2*)&g_att[(size_t)(off + qa) * CDIM + cc] = v;
        }
        if (qb < L) {
            float2 v = {o[nt][2] * i1, o[nt][3] * i1};
            *(float2*)&g_att[(size_t)(off + qb) * CDIM + cc] = v;
        }
    }
}

// ---------------------------------------------------------------------------
extern "C" void kernel_launch(void* const* d_in, const int* in_sizes, int n_in,
                              void* d_out, int out_size)
{
    const float* x      = (const float*)d_in[0];
    const int*   lens   = (const int*)d_in[2];
    const float* qkv_w  = (const float*)d_in[3];
    const float* qkv_b  = (const float*)d_in[4];
    const float* proj_w = (const float*)d_in[5];
    const float* proj_b = (const float*)d_in[6];
    float* out = (float*)d_out;

    float *qkv_p = nullptr, *att_p = nullptr;
    cudaGetSymbolAddress((void**)&qkv_p, g_qkv);
    cudaGetSymbolAddress((void**)&att_p, g_att);

    offsets_kernel<<<1, 1>>>(lens);
    gemm_bf16x2<<<dim3(768 / 64, TOTAL / 64), 128>>>(x, qkv_w, qkv_b, qkv_p,
                                                     TOTAL, 768, 256);
    attn_tf32<<<dim3(16, HEADS, BATCH), 128>>>(lens);
    gemm_bf16x2<<<dim3(256 / 64, TOTAL / 64), 128>>>(att_p, proj_w, proj_b, out,
                                                     TOTAL, 256, 256);
}

// round 3
// speedup vs baseline: 2.5231x; 1.1745x over previous
#include <cuda_runtime.h>
#include <cuda_bf16.h>
#include <cstdint>

#define TOTAL 6464
#define TPAD  6656          // >= TOTAL + 192 safety for padded tile reads
#define MROWS 6528          // 51 * 128 GEMM row tiles
#define CDIM  256
#define HEADS 8
#define BATCH 8

// ---------------- scratch (static device arrays, no runtime alloc) ----------
__device__ uint32_t g_q[TPAD * 256];   // tf32-rounded fp32 bits, Q pre-scaled
__device__ uint32_t g_k[TPAD * 256];
__device__ uint32_t g_v[TPAD * 256];
__device__ __nv_bfloat16 g_xh[TPAD * 256], g_xl[TPAD * 256];   // split input
__device__ __nv_bfloat16 g_ah[TPAD * 256], g_al[TPAD * 256];   // split attn out
__device__ __nv_bfloat16 g_wqh[768 * 256], g_wql[768 * 256];   // qkv_w^T split
__device__ __nv_bfloat16 g_wph[256 * 256], g_wpl[256 * 256];   // proj_w^T split
__device__ int g_off[BATCH + 1];

// ---------------- helpers ---------------------------------------------------
__device__ __forceinline__ uint32_t cvt_tf32(float f) {
    uint32_t u; asm("cvt.rna.tf32.f32 %0, %1;" : "=r"(u) : "f"(f)); return u;
}
__device__ __forceinline__ uint32_t packbf(float x, float y) {
    __nv_bfloat162 t = __floats2bfloat162_rn(x, y);
    return reinterpret_cast<uint32_t&>(t);
}
__device__ __forceinline__ float bfhi(float x) {
    return __bfloat162float(__float2bfloat16(x));
}
__device__ __forceinline__ void mma_tf32(float* c, uint32_t a0, uint32_t a1,
                                         uint32_t a2, uint32_t a3,
                                         uint32_t b0, uint32_t b1) {
    asm("mma.sync.aligned.m16n8k8.row.col.f32.tf32.tf32.f32 "
        "{%0,%1,%2,%3},{%4,%5,%6,%7},{%8,%9},{%0,%1,%2,%3};"
        : "+f"(c[0]), "+f"(c[1]), "+f"(c[2]), "+f"(c[3])
        : "r"(a0), "r"(a1), "r"(a2), "r"(a3), "r"(b0), "r"(b1));
}
__device__ __forceinline__ void mma_bf16(float* c, const uint32_t* a, const uint32_t* b) {
    asm("mma.sync.aligned.m16n8k16.row.col.f32.bf16.bf16.f32 "
        "{%0,%1,%2,%3},{%4,%5,%6,%7},{%8,%9},{%0,%1,%2,%3};"
        : "+f"(c[0]), "+f"(c[1]), "+f"(c[2]), "+f"(c[3])
        : "r"(a[0]), "r"(a[1]), "r"(a[2]), "r"(a[3]), "r"(b[0]), "r"(b[1]));
}
__device__ __forceinline__ void cpa16(void* dst_smem, const void* src) {
    uint32_t d = (uint32_t)__cvta_generic_to_shared(dst_smem);
    asm volatile("cp.async.cg.shared.global [%0], [%1], 16;" :: "r"(d), "l"(src));
}
#define CP_COMMIT asm volatile("cp.async.commit_group;")
#define CP_WAIT(n) asm volatile("cp.async.wait_group %0;" :: "n"(n))

// ---------------- tiny setup kernels ---------------------------------------
__global__ void offsets_kernel(const int* __restrict__ lens) {
    if (threadIdx.x == 0 && blockIdx.x == 0) {
        int s = 0;
        for (int i = 0; i < BATCH; i++) { g_off[i] = s; s += lens[i]; }
        g_off[BATCH] = s;
    }
}

// split x (fp32 -> bf16 hi/lo), vectorized
__global__ void split_x(const float4* __restrict__ x) {
    int i = blockIdx.x * blockDim.x + threadIdx.x;   // 0 .. TOTAL*64-1
    float4 v = x[i];
    uint32_t* H = (uint32_t*)g_xh;
    uint32_t* L = (uint32_t*)g_xl;
    float hx = bfhi(v.x), hy = bfhi(v.y), hz = bfhi(v.z), hw = bfhi(v.w);
    H[2 * i + 0] = packbf(v.x, v.y);
    H[2 * i + 1] = packbf(v.z, v.w);
    L[2 * i + 0] = packbf(v.x - hx, v.y - hy);
    L[2 * i + 1] = packbf(v.z - hz, v.w - hw);
}

// transpose-split weight: W[256,N] fp32 -> OH/OL [N][256] bf16
__global__ void tsplit(const float* __restrict__ W, int N,
                       __nv_bfloat16* __restrict__ OH,
                       __nv_bfloat16* __restrict__ OL) {
    __shared__ float t[32][33];
    int n0 = blockIdx.x * 32, k0 = blockIdx.y * 32;
    int tx = threadIdx.x, ty = threadIdx.y;   // 32 x 8
    #pragma unroll
    for (int j = 0; j < 4; j++)
        t[ty + 8 * j][tx] = W[(size_t)(k0 + ty + 8 * j) * N + n0 + tx];
    __syncthreads();
    #pragma unroll
    for (int j = 0; j < 4; j++) {
        float v = t[tx][ty + 8 * j];
        int n = n0 + ty + 8 * j, k = k0 + tx;
        float h = bfhi(v);
        OH[(size_t)n * 256 + k] = __float2bfloat16(v);
        OL[(size_t)n * 256 + k] = __float2bfloat16(v - h);
    }
}

// ---------------------------------------------------------------------------
// GEMM: C[M,N] = A @ B^T + bias, A split bf16 [rows][256], B split bf16 [N][256]
// (3-pass hi/lo). Tile 128x64, BK=32, 256 threads, cp.async double-buffered.
// mode 0: write fp32 to out (guard row<TOTAL).   mode 1: QKV epilogue -> g_q/k/v.
// ---------------------------------------------------------------------------
__global__ __launch_bounds__(256, 2) void gemm3(
    const __nv_bfloat16* __restrict__ Ah, const __nv_bfloat16* __restrict__ Al,
    const __nv_bfloat16* __restrict__ Bh, const __nv_bfloat16* __restrict__ Bl,
    const float* __restrict__ bias, float* __restrict__ out, int mode)
{
    extern __shared__ uint32_t sm[];
    uint32_t* AsH = sm;            // [2][128][20]
    uint32_t* AsL = sm + 5120;
    uint32_t* BsH = sm + 10240;    // [2][64][20]
    uint32_t* BsL = sm + 12800;

    const int tid = threadIdx.x, lane = tid & 31, wid = tid >> 5;
    const int g = lane >> 2, tig = lane & 3;
    const int wm = (wid >> 1) * 32, wn = (wid & 1) * 32;
    const int row0 = blockIdx.y * 128, col0 = blockIdx.x * 64;

    float c[2][4][4] = {};

    // -------- stage 0
    {
        int ko = 0;
        #pragma unroll
        for (int i = 0; i < 2; i++) {
            int idx = tid + i * 256;
            int r = idx >> 2, s = idx & 3;
            size_t sa = (size_t)(row0 + r) * 256 + ko + s * 8;
            cpa16(&AsH[r * 20 + s * 4], Ah + sa);
            cpa16(&AsL[r * 20 + s * 4], Al + sa);
        }
        int r = tid >> 2, s = tid & 3;
        size_t sb = (size_t)(col0 + r) * 256 + ko + s * 8;
        cpa16(&BsH[r * 20 + s * 4], Bh + sb);
        cpa16(&BsL[r * 20 + s * 4], Bl + sb);
        CP_COMMIT;
    }

    for (int it = 0; it < 8; it++) {
        if (it < 7) {
            int buf = (it + 1) & 1, ko = (it + 1) * 32;
            #pragma unroll
            for (int i = 0; i < 2; i++) {
                int idx = tid + i * 256;
                int r = idx >> 2, s = idx & 3;
                size_t sa = (size_t)(row0 + r) * 256 + ko + s * 8;
                cpa16(&AsH[buf * 2560 + r * 20 + s * 4], Ah + sa);
                cpa16(&AsL[buf * 2560 + r * 20 + s * 4], Al + sa);
            }
            int r = tid >> 2, s = tid & 3;
            size_t sb = (size_t)(col0 + r) * 256 + ko + s * 8;
            cpa16(&BsH[buf * 1280 + r * 20 + s * 4], Bh + sb);
            cpa16(&BsL[buf * 1280 + r * 20 + s * 4], Bl + sb);
            CP_COMMIT;
            CP_WAIT(1);
        } else {
            CP_WAIT(0);
        }
        __syncthreads();

        const int buf = it & 1;
        const uint32_t* aH = &AsH[buf * 2560];
        const uint32_t* aL = &AsL[buf * 2560];
        const uint32_t* bH = &BsH[buf * 1280];
        const uint32_t* bL = &BsL[buf * 1280];

        #pragma unroll
        for (int ks = 0; ks < 2; ks++) {
            uint32_t ah[2][4], al[2][4], bh[4][2], bl[4][2];
            #pragma unroll
            for (int mt = 0; mt < 2; mt++) {
                int b0 = (wm + mt * 16 + g) * 20 + ks * 8;
                int b1 = (wm + mt * 16 + g + 8) * 20 + ks * 8;
                ah[mt][0] = aH[b0 + tig];     ah[mt][1] = aH[b1 + tig];
                ah[mt][2] = aH[b0 + tig + 4]; ah[mt][3] = aH[b1 + tig + 4];
                al[mt][0] = aL[b0 + tig];     al[mt][1] = aL[b1 + tig];
                al[mt][2] = aL[b0 + tig + 4]; al[mt][3] = aL[b1 + tig + 4];
            }
            #pragma unroll
            for (int nt = 0; nt < 4; nt++) {
                int n = (wn + nt * 8 + g) * 20 + ks * 8;
                bh[nt][0] = bH[n + tig]; bh[nt][1] = bH[n + tig + 4];
                bl[nt][0] = bL[n + tig]; bl[nt][1] = bL[n + tig + 4];
            }
            #pragma unroll
            for (int mt = 0; mt < 2; mt++)
                #pragma unroll
                for (int nt = 0; nt < 4; nt++) {
                    mma_bf16(c[mt][nt], ah[mt], bh[nt]);
                    mma_bf16(c[mt][nt], ah[mt], bl[nt]);
                    mma_bf16(c[mt][nt], al[mt], bh[nt]);
                }
        }
        __syncthreads();
    }

    // -------- epilogue
    const float sc = 0.17677669529663687f;   // 32^-0.5
    #pragma unroll
    for (int mt = 0; mt < 2; mt++)
        #pragma unroll
        for (int nt = 0; nt < 4; nt++) {
            int r = row0 + wm + mt * 16 + g;
            int j = col0 + wn + nt * 8 + 2 * tig;
            float2 bv = *(const float2*)&bias[j];
            float v0 = c[mt][nt][0] + bv.x, v1 = c[mt][nt][1] + bv.y;
            float v2 = c[mt][nt][2] + bv.x, v3 = c[mt][nt][3] + bv.y;
            if (mode == 0) {
                if (r < TOTAL) { float2 o = {v0, v1};
                    *(float2*)&out[(size_t)r * 256 + j] = o; }
                if (r + 8 < TOTAL) { float2 o = {v2, v3};
                    *(float2*)&out[(size_t)(r + 8) * 256 + j] = o; }
            } else {
                int arr = j >> 8, jc = j & 255;
                uint32_t* dst = (arr == 0) ? g_q : (arr == 1) ? g_k : g_v;
                if (arr == 0) { v0 *= sc; v1 *= sc; v2 *= sc; v3 *= sc; }
                uint2 p0 = {cvt_tf32(v0), cvt_tf32(v1)};
                uint2 p1 = {cvt_tf32(v2), cvt_tf32(v3)};
                *(uint2*)&dst[(size_t)r * 256 + jc] = p0;
                *(uint2*)&dst[(size_t)(r + 8) * 256 + jc] = p1;
            }
        }
}

// ---------------------------------------------------------------------------
// Ragged flash attention, tf32 mma. Q-tile 128 (8 warps x m16), K-chunk 64,
// cp.async double-buffered K/V, Q in registers, P via quad-shuffles (no smem).
// Epilogue writes bf16 hi/lo split directly for the proj GEMM.
// grid = (8 qtiles, 8 heads, 8 batches), block 256.
// ---------------------------------------------------------------------------
__global__ __launch_bounds__(256, 2) void attn3(const int* __restrict__ lens)
{
    const int qt = blockIdx.x, h = blockIdx.y, b = blockIdx.z;
    const int L = lens[b];
    const int q0 = qt * 128;
    if (q0 >= L) return;
    const int off = g_off[b];

    __shared__ uint32_t Ks[2][64][36];
    __shared__ uint32_t Vs[2][64][36];

    const int tid = threadIdx.x, lane = tid & 31, wid = tid >> 5;
    const int g = lane >> 2, tig = lane & 3;
    const int m0 = wid * 16;

    // Q fragments straight from global (already scaled + tf32-rounded)
    uint32_t qa_[4][4];
    {
        int rowA = off + q0 + m0 + g, rowB = rowA + 8;
        const uint32_t* gq = g_q;
        #pragma unroll
        for (int ks = 0; ks < 4; ks++) {
            int cbase = h * 32 + ks * 8;
            qa_[ks][0] = gq[(size_t)rowA * 256 + cbase + tig];
            qa_[ks][1] = gq[(size_t)rowB * 256 + cbase + tig];
            qa_[ks][2] = gq[(size_t)rowA * 256 + cbase + tig + 4];
            qa_[ks][3] = gq[(size_t)rowB * 256 + cbase + tig + 4];
        }
    }

    float o[4][4];
    #pragma unroll
    for (int nt = 0; nt < 4; nt++)
        #pragma unroll
        for (int i = 0; i < 4; i++) o[nt][i] = 0.f;
    float mr0 = -1e30f, mr1 = -1e30f, l0 = 0.f, l1 = 0.f;

    const int nch = (L + 63) >> 6;

    // stage chunk 0
    {
        #pragma unroll
        for (int i = 0; i < 2; i++) {
            int idx = tid + i * 256;
            int r = idx >> 3, s = idx & 7;
            size_t src = (size_t)(off + r) * 256 + h * 32 + s * 4;
            cpa16(&Ks[0][r][s * 4], g_k + src);
            cpa16(&Vs[0][r][s * 4], g_v + src);
        }
        CP_COMMIT;
    }

    for (int c = 0; c < nch; c++) {
        if (c + 1 < nch) {
            int buf = (c + 1) & 1, k0n = (c + 1) * 64;
            #pragma unroll
            for (int i = 0; i < 2; i++) {
                int idx = tid + i * 256;
                int r = idx >> 3, s = idx & 7;
                size_t src = (size_t)(off + k0n + r) * 256 + h * 32 + s * 4;
                cpa16(&Ks[buf][r][s * 4], g_k + src);
                cpa16(&Vs[buf][r][s * 4], g_v + src);
            }
            CP_COMMIT;
            CP_WAIT(1);
        } else {
            CP_WAIT(0);
        }
        __syncthreads();

        const int buf = c & 1;
        const int k0 = c * 64;

        // S = Q @ K^T
        float s_[8][4] = {};
        #pragma unroll
        for (int ks = 0; ks < 4; ks++) {
            #pragma unroll
            for (int jt = 0; jt < 8; jt++) {
                uint32_t b0 = Ks[buf][jt * 8 + g][ks * 8 + tig];
                uint32_t b1 = Ks[buf][jt * 8 + g][ks * 8 + tig + 4];
                mma_tf32(s_[jt], qa_[ks][0], qa_[ks][1], qa_[ks][2], qa_[ks][3], b0, b1);
            }
        }
        // ragged key mask
        if (k0 + 64 > L) {
            #pragma unroll
            for (int jt = 0; jt < 8; jt++) {
                int col = k0 + jt * 8 + 2 * tig;
                if (col >= L)     { s_[jt][0] = -1e9f; s_[jt][2] = -1e9f; }
                if (col + 1 >= L) { s_[jt][1] = -1e9f; s_[jt][3] = -1e9f; }
            }
        }
        // online softmax
        float mx0 = -1e30f, mx1 = -1e30f;
        #pragma unroll
        for (int jt = 0; jt < 8; jt++) {
            mx0 = fmaxf(mx0, fmaxf(s_[jt][0], s_[jt][1]));
            mx1 = fmaxf(mx1, fmaxf(s_[jt][2], s_[jt][3]));
        }
        mx0 = fmaxf(mx0, __shfl_xor_sync(0xffffffffu, mx0, 1));
        mx0 = fmaxf(mx0, __shfl_xor_sync(0xffffffffu, mx0, 2));
        mx1 = fmaxf(mx1, __shfl_xor_sync(0xffffffffu, mx1, 1));
        mx1 = fmaxf(mx1, __shfl_xor_sync(0xffffffffu, mx1, 2));
        float mn0 = fmaxf(mr0, mx0), mn1 = fmaxf(mr1, mx1);
        float cr0 = __expf(mr0 - mn0), cr1 = __expf(mr1 - mn1);
        mr0 = mn0; mr1 = mn1;
        float ps0 = 0.f, ps1 = 0.f;
        #pragma unroll
        for (int jt = 0; jt < 8; jt++) {
            s_[jt][0] = __expf(s_[jt][0] - mn0); ps0 += s_[jt][0];
            s_[jt][1] = __expf(s_[jt][1] - mn0); ps0 += s_[jt][1];
            s_[jt][2] = __expf(s_[jt][2] - mn1); ps1 += s_[jt][2];
            s_[jt][3] = __expf(s_[jt][3] - mn1); ps1 += s_[jt][3];
        }
        l0 = l0 * cr0 + ps0;
        l1 = l1 * cr1 + ps1;
        #pragma unroll
        for (int nt = 0; nt < 4; nt++) {
            o[nt][0] *= cr0; o[nt][1] *= cr0;
            o[nt][2] *= cr1; o[nt][3] *= cr1;
        }
        // O += P @ V   (P fragment built with quad shuffles)
        #pragma unroll
        for (int ks = 0; ks < 8; ks++) {
            int srcA = (lane & 28) | (tig >> 1);
            int srcB = srcA + 2;
            float xa0 = __shfl_sync(0xffffffffu, s_[ks][0], srcA);
            float xa1 = __shfl_sync(0xffffffffu, s_[ks][1], srcA);
            float xa2 = __shfl_sync(0xffffffffu, s_[ks][2], srcA);
            float xa3 = __shfl_sync(0xffffffffu, s_[ks][3], srcA);
            float xb0 = __shfl_sync(0xffffffffu, s_[ks][0], srcB);
            float xb1 = __shfl_sync(0xffffffffu, s_[ks][1], srcB);
            float xb2 = __shfl_sync(0xffffffffu, s_[ks][2], srcB);
            float xb3 = __shfl_sync(0xffffffffu, s_[ks][3], srcB);
            bool odd = (tig & 1);
            uint32_t a0 = cvt_tf32(odd ? xa1 : xa0);
            uint32_t a1 = cvt_tf32(odd ? xa3 : xa2);
            uint32_t a2 = cvt_tf32(odd ? xb1 : xb0);
            uint32_t a3 = cvt_tf32(odd ? xb3 : xb2);
            #pragma unroll
            for (int nt = 0; nt < 4; nt++) {
                uint32_t b0 = Vs[buf][ks * 8 + tig][nt * 8 + g];
                uint32_t b1 = Vs[buf][ks * 8 + tig + 4][nt * 8 + g];
                mma_tf32(o[nt], a0, a1, a2, a3, b0, b1);
            }
        }
        __syncthreads();
    }

    l0 += __shfl_xor_sync(0xffffffffu, l0, 1);
    l0 += __shfl_xor_sync(0xffffffffu, l0, 2);
    l1 += __shfl_xor_sync(0xffffffffu, l1, 1);
    l1 += __shfl_xor_sync(0xffffffffu, l1, 2);
    float i0 = 1.f / l0, i1 = 1.f / l1;

    int qa = q0 + m0 + g, qb = qa + 8;
    uint32_t* AH = (uint32_t*)g_ah;
    uint32_t* AL = (uint32_t*)g_al;
    #pragma unroll
    for (int nt = 0; nt < 4; nt++) {
        int ci = h * 16 + nt * 4 + tig;   // u32 col (pairs of bf16)
        if (qa < L) {
            float v0 = o[nt][0] * i0, v1 = o[nt][1] * i0;
            float h0 = bfhi(v0), h1 = bfhi(v1);
            AH[(size_t)(off + qa) * 128 + ci] = packbf(v0, v1);
            AL[(size_t)(off + qa) * 128 + ci] = packbf(v0 - h0, v1 - h1);
        }
        if (qb < L) {
            float v2 = o[nt][2] * i1, v3 = o[nt][3] * i1;
            float h2 = bfhi(v2), h3 = bfhi(v3);
            AH[(size_t)(off + qb) * 128 + ci] = packbf(v2, v3);
            AL[(size_t)(off + qb) * 128 + ci] = packbf(v2 - h2, v3 - h3);
        }
    }
}

// ---------------------------------------------------------------------------
extern "C" void kernel_launch(void* const* d_in, const int* in_sizes, int n_in,
                              void* d_out, int out_size)
{
    const float* x      = (const float*)d_in[0];
    const int*   lens   = (const int*)d_in[2];
    const float* qkv_w  = (const float*)d_in[3];
    const float* qkv_b  = (const float*)d_in[4];
    const float* proj_w = (const float*)d_in[5];
    const float* proj_b = (const float*)d_in[6];
    float* out = (float*)d_out;

    __nv_bfloat16 *xh, *xl, *ah, *al, *wqh, *wql, *wph, *wpl;
    cudaGetSymbolAddress((void**)&xh,  g_xh);
    cudaGetSymbolAddress((void**)&xl,  g_xl);
    cudaGetSymbolAddress((void**)&ah,  g_ah);
    cudaGetSymbolAddress((void**)&al,  g_al);
    cudaGetSymbolAddress((void**)&wqh, g_wqh);
    cudaGetSymbolAddress((void**)&wql, g_wql);
    cudaGetSymbolAddress((void**)&wph, g_wph);
    cudaGetSymbolAddress((void**)&wpl, g_wpl);

    cudaFuncSetAttribute(gemm3, cudaFuncAttributeMaxDynamicSharedMemorySize, 61440);

    offsets_kernel<<<1, 1>>>(lens);
    split_x<<<TOTAL * 64 / 256, 256>>>((const float4*)x);
    tsplit<<<dim3(24, 8), dim3(32, 8)>>>(qkv_w, 768, wqh, wql);
    tsplit<<<dim3(8, 8),  dim3(32, 8)>>>(proj_w, 256, wph, wpl);

    gemm3<<<dim3(12, 51), 256, 61440>>>(xh, xl, wqh, wql, qkv_b, nullptr, 1);
    attn3<<<dim3(8, HEADS, BATCH), 256>>>(lens);
    gemm3<<<dim3(4, 51), 256, 61440>>>(ah, al, wph, wpl, proj_b, out, 0);
}

// round 4
// speedup vs baseline: 3.2059x; 1.2706x over previous
#include <cuda_runtime.h>
#include <cuda_bf16.h>
#include <cuda_fp16.h>
#include <cstdint>

#define TOTAL 6464
#define TPAD  6656
#define CDIM  256
#define HEADS 8
#define BATCH 8

// ---------------- scratch (static device arrays, zero-initialized) ----------
__device__ uint32_t g_q16[TPAD * 128];          // fp16x2 [token][128], Q pre-scaled by sc*log2e
__device__ uint32_t g_k16[TPAD * 128];          // fp16x2 [token][128]
__device__ __half   g_vt[HEADS * 32 * TPAD];    // V transposed: [head][dim][token]
__device__ __nv_bfloat16 g_xh[TPAD * 256], g_xl[TPAD * 256];
__device__ __nv_bfloat16 g_ah[TPAD * 256], g_al[TPAD * 256];
__device__ __nv_bfloat16 g_wqh[768 * 256], g_wql[768 * 256];
__device__ __nv_bfloat16 g_wph[256 * 256], g_wpl[256 * 256];
__device__ int g_off[BATCH + 1];

// ---------------- helpers ---------------------------------------------------
__device__ __forceinline__ uint32_t packbf(float x, float y) {
    __nv_bfloat162 t = __floats2bfloat162_rn(x, y);
    return reinterpret_cast<uint32_t&>(t);
}
__device__ __forceinline__ uint32_t packh2(float x, float y) {
    __half2 t = __floats2half2_rn(x, y);
    return reinterpret_cast<uint32_t&>(t);
}
__device__ __forceinline__ float bfhi(float x) {
    return __bfloat162float(__float2bfloat16(x));
}
__device__ __forceinline__ float ex2(float x) {
    float y; asm("ex2.approx.f32 %0, %1;" : "=f"(y) : "f"(x)); return y;
}
__device__ __forceinline__ void mma_bf16(float* c, const uint32_t* a, const uint32_t* b) {
    asm("mma.sync.aligned.m16n8k16.row.col.f32.bf16.bf16.f32 "
        "{%0,%1,%2,%3},{%4,%5,%6,%7},{%8,%9},{%0,%1,%2,%3};"
        : "+f"(c[0]), "+f"(c[1]), "+f"(c[2]), "+f"(c[3])
        : "r"(a[0]), "r"(a[1]), "r"(a[2]), "r"(a[3]), "r"(b[0]), "r"(b[1]));
}
__device__ __forceinline__ void mma_f16(float* c, uint32_t a0, uint32_t a1,
                                        uint32_t a2, uint32_t a3,
                                        uint32_t b0, uint32_t b1) {
    asm("mma.sync.aligned.m16n8k16.row.col.f32.f16.f16.f32 "
        "{%0,%1,%2,%3},{%4,%5,%6,%7},{%8,%9},{%0,%1,%2,%3};"
        : "+f"(c[0]), "+f"(c[1]), "+f"(c[2]), "+f"(c[3])
        : "r"(a0), "r"(a1), "r"(a2), "r"(a3), "r"(b0), "r"(b1));
}
__device__ __forceinline__ void cpa16(void* dst_smem, const void* src) {
    uint32_t d = (uint32_t)__cvta_generic_to_shared(dst_smem);
    asm volatile("cp.async.cg.shared.global [%0], [%1], 16;" :: "r"(d), "l"(src));
}
__device__ __forceinline__ void cpa8(void* dst_smem, const void* src) {
    uint32_t d = (uint32_t)__cvta_generic_to_shared(dst_smem);
    asm volatile("cp.async.ca.shared.global [%0], [%1], 8;" :: "r"(d), "l"(src));
}
#define CP_COMMIT asm volatile("cp.async.commit_group;")
#define CP_WAIT(n) asm volatile("cp.async.wait_group %0;" :: "n"(n))

// ---------------- setup: split x + offsets ----------------------------------
__global__ void split_x(const float4* __restrict__ x, const int* __restrict__ lens) {
    int i = blockIdx.x * blockDim.x + threadIdx.x;   // 0 .. TOTAL*64-1
    if (i == 0) {
        int s = 0;
        for (int k = 0; k < BATCH; k++) { g_off[k] = s; s += lens[k]; }
        g_off[BATCH] = s;
    }
    float4 v = x[i];
    uint32_t* H = (uint32_t*)g_xh;
    uint32_t* L = (uint32_t*)g_xl;
    float hx = bfhi(v.x), hy = bfhi(v.y), hz = bfhi(v.z), hw = bfhi(v.w);
    H[2 * i + 0] = packbf(v.x, v.y);
    H[2 * i + 1] = packbf(v.z, v.w);
    L[2 * i + 0] = packbf(v.x - hx, v.y - hy);
    L[2 * i + 1] = packbf(v.z - hz, v.w - hw);
}

// transpose-split both weights in one launch (z=0: qkv N=768, z=1: proj N=256)
__global__ void tsplit2(const float* __restrict__ Wq, const float* __restrict__ Wp) {
    const float* W; __nv_bfloat16 *OH, *OL; int N;
    if (blockIdx.z == 0) { W = Wq; OH = g_wqh; OL = g_wql; N = 768; }
    else                 { W = Wp; OH = g_wph; OL = g_wpl; N = 256;
                           if (blockIdx.x >= 8) return; }
    __shared__ float t[32][33];
    int n0 = blockIdx.x * 32, k0 = blockIdx.y * 32;
    int tx = threadIdx.x, ty = threadIdx.y;   // 32 x 8
    #pragma unroll
    for (int j = 0; j < 4; j++)
        t[ty + 8 * j][tx] = W[(size_t)(k0 + ty + 8 * j) * N + n0 + tx];
    __syncthreads();
    #pragma unroll
    for (int j = 0; j < 4; j++) {
        float v = t[tx][ty + 8 * j];
        int n = n0 + ty + 8 * j, k = k0 + tx;
        float h = bfhi(v);
        OH[(size_t)n * 256 + k] = __float2bfloat16(v);
        OL[(size_t)n * 256 + k] = __float2bfloat16(v - h);
    }
}

// ---------------------------------------------------------------------------
// GEMM: C = A @ B^T + bias, split-bf16 3-pass. Tile 128x64, BK=32, 256 thr,
// cp.async double-buffered. mode 0: fp32 out. mode 1: QKV epilogue ->
// Q,K fp16 row-major (Q pre-scaled by sc*log2e), V fp16 transposed per head.
// ---------------------------------------------------------------------------
__global__ __launch_bounds__(256, 2) void gemm3(
    const __nv_bfloat16* __restrict__ Ah, const __nv_bfloat16* __restrict__ Al,
    const __nv_bfloat16* __restrict__ Bh, const __nv_bfloat16* __restrict__ Bl,
    const float* __restrict__ bias, float* __restrict__ out, int mode)
{
    extern __shared__ uint32_t sm[];
    uint32_t* AsH = sm;            // [2][128][20]
    uint32_t* AsL = sm + 5120;
    uint32_t* BsH = sm + 10240;    // [2][64][20]
    uint32_t* BsL = sm + 12800;

    const int tid = threadIdx.x, lane = tid & 31, wid = tid >> 5;
    const int g = lane >> 2, tig = lane & 3;
    const int wm = (wid >> 1) * 32, wn = (wid & 1) * 32;
    const int row0 = blockIdx.y * 128, col0 = blockIdx.x * 64;

    float c[2][4][4] = {};

    {
        #pragma unroll
        for (int i = 0; i < 2; i++) {
            int idx = tid + i * 256;
            int r = idx >> 2, s = idx & 3;
            size_t sa = (size_t)(row0 + r) * 256 + s * 8;
            cpa16(&AsH[r * 20 + s * 4], Ah + sa);
            cpa16(&AsL[r * 20 + s * 4], Al + sa);
        }
        int r = tid >> 2, s = tid & 3;
        size_t sb = (size_t)(col0 + r) * 256 + s * 8;
        cpa16(&BsH[r * 20 + s * 4], Bh + sb);
        cpa16(&BsL[r * 20 + s * 4], Bl + sb);
        CP_COMMIT;
    }

    for (int it = 0; it < 8; it++) {
        if (it < 7) {
            int buf = (it + 1) & 1, ko = (it + 1) * 32;
            #pragma unroll
            for (int i = 0; i < 2; i++) {
                int idx = tid + i * 256;
                int r = idx >> 2, s = idx & 3;
                size_t sa = (size_t)(row0 + r) * 256 + ko + s * 8;
                cpa16(&AsH[buf * 2560 + r * 20 + s * 4], Ah + sa);
                cpa16(&AsL[buf * 2560 + r * 20 + s * 4], Al + sa);
            }
            int r = tid >> 2, s = tid & 3;
            size_t sb = (size_t)(col0 + r) * 256 + ko + s * 8;
            cpa16(&BsH[buf * 1280 + r * 20 + s * 4], Bh + sb);
            cpa16(&BsL[buf * 1280 + r * 20 + s * 4], Bl + sb);
            CP_COMMIT;
            CP_WAIT(1);
        } else {
            CP_WAIT(0);
        }
        __syncthreads();

        const int buf = it & 1;
        const uint32_t* aH = &AsH[buf * 2560];
        const uint32_t* aL = &AsL[buf * 2560];
        const uint32_t* bH = &BsH[buf * 1280];
        const uint32_t* bL = &BsL[buf * 1280];

        #pragma unroll
        for (int ks = 0; ks < 2; ks++) {
            uint32_t ah[2][4], al[2][4], bh[4][2], bl[4][2];
            #pragma unroll
            for (int mt = 0; mt < 2; mt++) {
                int b0 = (wm + mt * 16 + g) * 20 + ks * 8;
                int b1 = (wm + mt * 16 + g + 8) * 20 + ks * 8;
                ah[mt][0] = aH[b0 + tig];     ah[mt][1] = aH[b1 + tig];
                ah[mt][2] = aH[b0 + tig + 4]; ah[mt][3] = aH[b1 + tig + 4];
                al[mt][0] = aL[b0 + tig];     al[mt][1] = aL[b1 + tig];
                al[mt][2] = aL[b0 + tig + 4]; al[mt][3] = aL[b1 + tig + 4];
            }
            #pragma unroll
            for (int nt = 0; nt < 4; nt++) {
                int n = (wn + nt * 8 + g) * 20 + ks * 8;
                bh[nt][0] = bH[n + tig]; bh[nt][1] = bH[n + tig + 4];
                bl[nt][0] = bL[n + tig]; bl[nt][1] = bL[n + tig + 4];
            }
            #pragma unroll
            for (int mt = 0; mt < 2; mt++)
                #pragma unroll
                for (int nt = 0; nt < 4; nt++) {
                    mma_bf16(c[mt][nt], ah[mt], bh[nt]);
                    mma_bf16(c[mt][nt], ah[mt], bl[nt]);
                    mma_bf16(c[mt][nt], al[mt], bh[nt]);
                }
        }
        __syncthreads();
    }

    const float sc = 0.17677669529663687f * 1.4426950408889634f;  // hd^-0.5 * log2(e)
    #pragma unroll
    for (int mt = 0; mt < 2; mt++)
        #pragma unroll
        for (int nt = 0; nt < 4; nt++) {
            int r = row0 + wm + mt * 16 + g;
            int j = col0 + wn + nt * 8 + 2 * tig;
            float2 bv = *(const float2*)&bias[j];
            float v0 = c[mt][nt][0] + bv.x, v1 = c[mt][nt][1] + bv.y;
            float v2 = c[mt][nt][2] + bv.x, v3 = c[mt][nt][3] + bv.y;
            if (mode == 0) {
                if (r < TOTAL) { float2 o = {v0, v1};
                    *(float2*)&out[(size_t)r * 256 + j] = o; }
                if (r + 8 < TOTAL) { float2 o = {v2, v3};
                    *(float2*)&out[(size_t)(r + 8) * 256 + j] = o; }
            } else {
                int arr = j >> 8, jc = j & 255;
                if (arr == 0) {
                    g_q16[(size_t)r * 128 + (jc >> 1)] = packh2(v0 * sc, v1 * sc);
                    g_q16[(size_t)(r + 8) * 128 + (jc >> 1)] = packh2(v2 * sc, v3 * sc);
                } else if (arr == 1) {
                    g_k16[(size_t)r * 128 + (jc >> 1)] = packh2(v0, v1);
                    g_k16[(size_t)(r + 8) * 128 + (jc >> 1)] = packh2(v2, v3);
                } else {
                    int hh = jc >> 5, d = jc & 31;
                    size_t base = (size_t)(hh * 32 + d) * TPAD;
                    g_vt[base + r]            = __float2half(v0);
                    g_vt[base + TPAD + r]     = __float2half(v1);
                    g_vt[base + r + 8]        = __float2half(v2);
                    g_vt[base + TPAD + r + 8] = __float2half(v3);
                }
            }
        }
}

// ---------------------------------------------------------------------------
// Ragged flash attention, fp16 m16n8k16. Q-tile 128 (8 warps), K-chunk 64.
// Q fragments in registers; K [key][dim], V^T [dim][key] in smem via cp.async
// double-buffer. P fragments = direct half2 packs of the S accumulator
// (C-layout == A-layout). log2-domain softmax (single EX2 per element).
// ---------------------------------------------------------------------------
__global__ __launch_bounds__(256, 2) void attn4(const int* __restrict__ lens)
{
    const int qt = blockIdx.x, h = blockIdx.y, b = blockIdx.z;
    const int L = lens[b];
    const int q0 = qt * 128;
    if (q0 >= L) return;
    const int off = g_off[b];

    __shared__ uint32_t Ks[2][64][20];   // [key][dim-pairs], stride 20 (conflict-free)
    __shared__ uint32_t Vt[2][32][36];   // [dim][key-pairs], stride 36 (conflict-free)

    const int tid = threadIdx.x, lane = tid & 31, wid = tid >> 5;
    const int g = lane >> 2, tig = lane & 3;
    const int m0 = wid * 16;

    // Q fragments (already fp16, scaled by hd^-0.5*log2e)
    uint32_t qf[2][4];
    {
        size_t rA = (size_t)(off + q0 + m0 + g) * 128;
        size_t rB = rA + 8 * 128;
        #pragma unroll
        for (int ks = 0; ks < 2; ks++) {
            int cb = h * 16 + ks * 8;
            qf[ks][0] = g_q16[rA + cb + tig];
            qf[ks][1] = g_q16[rB + cb + tig];
            qf[ks][2] = g_q16[rA + cb + tig + 4];
            qf[ks][3] = g_q16[rB + cb + tig + 4];
        }
    }

    float o[4][4];
    #pragma unroll
    for (int nt = 0; nt < 4; nt++)
        #pragma unroll
        for (int i = 0; i < 4; i++) o[nt][i] = 0.f;
    float mr0 = -1e30f, mr1 = -1e30f, l0 = 0.f, l1 = 0.f;

    const int nch = (L + 63) >> 6;

    // stage chunk 0
    #pragma unroll
    for (int i = 0; i < 3; i++) {
        int idx = tid + i * 256;
        if (idx < 256) {
            int r = idx >> 2, s = idx & 3;
            cpa16(&Ks[0][r][s * 4], g_k16 + (size_t)(off + r) * 128 + h * 16 + s * 4);
        } else {
            int j = idx - 256;
            int d = j >> 4, s = j & 15;
            cpa8(&Vt[0][d][s * 2], g_vt + (size_t)(h * 32 + d) * TPAD + off + s * 4);
        }
    }
    CP_COMMIT;

    for (int c = 0; c < nch; c++) {
        if (c + 1 < nch) {
            int buf = (c + 1) & 1, k0n = (c + 1) * 64;
            #pragma unroll
            for (int i = 0; i < 3; i++) {
                int idx = tid + i * 256;
                if (idx < 256) {
                    int r = idx >> 2, s = idx & 3;
                    cpa16(&Ks[buf][r][s * 4],
                          g_k16 + (size_t)(off + k0n + r) * 128 + h * 16 + s * 4);
                } else {
                    int j = idx - 256;
                    int d = j >> 4, s = j & 15;
                    cpa8(&Vt[buf][d][s * 2],
                         g_vt + (size_t)(h * 32 + d) * TPAD + off + k0n + s * 4);
                }
            }
            CP_COMMIT;
            CP_WAIT(1);
        } else {
            CP_WAIT(0);
        }
        __syncthreads();

        const int buf = c & 1;
        const int k0 = c * 64;

        // S = Q @ K^T (log2 domain): 2 ksteps x 8 key-tiles
        float s_[8][4] = {};
        #pragma unroll
        for (int ks = 0; ks < 2; ks++) {
            #pragma unroll
            for (int jt = 0; jt < 8; jt++) {
                uint32_t b0 = Ks[buf][jt * 8 + g][ks * 8 + tig];
                uint32_t b1 = Ks[buf][jt * 8 + g][ks * 8 + tig + 4];
                mma_f16(s_[jt], qf[ks][0], qf[ks][1], qf[ks][2], qf[ks][3], b0, b1);
            }
        }
        // ragged key mask
        if (k0 + 64 > L) {
            #pragma unroll
            for (int jt = 0; jt < 8; jt++) {
                int col = k0 + jt * 8 + 2 * tig;
                if (col >= L)     { s_[jt][0] = -1e9f; s_[jt][2] = -1e9f; }
                if (col + 1 >= L) { s_[jt][1] = -1e9f; s_[jt][3] = -1e9f; }
            }
        }
        // online softmax (base-2)
        float mx0 = -1e30f, mx1 = -1e30f;
        #pragma unroll
        for (int jt = 0; jt < 8; jt++) {
            mx0 = fmaxf(mx0, fmaxf(s_[jt][0], s_[jt][1]));
            mx1 = fmaxf(mx1, fmaxf(s_[jt][2], s_[jt][3]));
        }
        mx0 = fmaxf(mx0, __shfl_xor_sync(0xffffffffu, mx0, 1));
        mx0 = fmaxf(mx0, __shfl_xor_sync(0xffffffffu, mx0, 2));
        mx1 = fmaxf(mx1, __shfl_xor_sync(0xffffffffu, mx1, 1));
        mx1 = fmaxf(mx1, __shfl_xor_sync(0xffffffffu, mx1, 2));
        float mn0 = fmaxf(mr0, mx0), mn1 = fmaxf(mr1, mx1);
        float cr0 = ex2(mr0 - mn0), cr1 = ex2(mr1 - mn1);
        mr0 = mn0; mr1 = mn1;
        float ps0 = 0.f, ps1 = 0.f;
        #pragma unroll
        for (int jt = 0; jt < 8; jt++) {
            s_[jt][0] = ex2(s_[jt][0] - mn0); ps0 += s_[jt][0];
            s_[jt][1] = ex2(s_[jt][1] - mn0); ps0 += s_[jt][1];
            s_[jt][2] = ex2(s_[jt][2] - mn1); ps1 += s_[jt][2];
            s_[jt][3] = ex2(s_[jt][3] - mn1); ps1 += s_[jt][3];
        }
        l0 = l0 * cr0 + ps0;
        l1 = l1 * cr1 + ps1;
        #pragma unroll
        for (int nt = 0; nt < 4; nt++) {
            o[nt][0] *= cr0; o[nt][1] *= cr0;
            o[nt][2] *= cr1; o[nt][3] *= cr1;
        }
        // O += P @ V : P fragments are direct packs of S (C-layout == A-layout)
        #pragma unroll
        for (int t = 0; t < 4; t++) {
            uint32_t a0 = packh2(s_[2 * t][0],     s_[2 * t][1]);
            uint32_t a1 = packh2(s_[2 * t][2],     s_[2 * t][3]);
            uint32_t a2 = packh2(s_[2 * t + 1][0], s_[2 * t + 1][1]);
            uint32_t a3 = packh2(s_[2 * t + 1][2], s_[2 * t + 1][3]);
            #pragma unroll
            for (int nt = 0; nt < 4; nt++) {
                uint32_t b0 = Vt[buf][nt * 8 + g][8 * t + tig];
                uint32_t b1 = Vt[buf][nt * 8 + g][8 * t + 4 + tig];
                mma_f16(o[nt], a0, a1, a2, a3, b0, b1);
            }
        }
        __syncthreads();
    }

    l0 += __shfl_xor_sync(0xffffffffu, l0, 1);
    l0 += __shfl_xor_sync(0xffffffffu, l0, 2);
    l1 += __shfl_xor_sync(0xffffffffu, l1, 1);
    l1 += __shfl_xor_sync(0xffffffffu, l1, 2);
    float i0 = 1.f / l0, i1 = 1.f / l1;

    int qa = q0 + m0 + g, qb = qa + 8;
    uint32_t* AH = (uint32_t*)g_ah;
    uint32_t* AL = (uint32_t*)g_al;
    #pragma unroll
    for (int nt = 0; nt < 4; nt++) {
        int ci = h * 16 + nt * 4 + tig;
        if (qa < L) {
            float v0 = o[nt][0] * i0, v1 = o[nt][1] * i0;
            float h0 = bfhi(v0), h1 = bfhi(v1);
            AH[(size_t)(off + qa) * 128 + ci] = packbf(v0, v1);
            AL[(size_t)(off + qa) * 128 + ci] = packbf(v0 - h0, v1 - h1);
        }
        if (qb < L) {
            float v2 = o[nt][2] * i1, v3 = o[nt][3] * i1;
            float h2 = bfhi(v2), h3 = bfhi(v3);
            AH[(size_t)(off + qb) * 128 + ci] = packbf(v2, v3);
            AL[(size_t)(off + qb) * 128 + ci] = packbf(v2 - h2, v3 - h3);
        }
    }
}

// ---------------------------------------------------------------------------
extern "C" void kernel_launch(void* const* d_in, const int* in_sizes, int n_in,
                              void* d_out, int out_size)
{
    const float* x      = (const float*)d_in[0];
    const int*   lens   = (const int*)d_in[2];
    const float* qkv_w  = (const float*)d_in[3];
    const float* qkv_b  = (const float*)d_in[4];
    const float* proj_w = (const float*)d_in[5];
    const float* proj_b = (const float*)d_in[6];
    float* out = (float*)d_out;

    __nv_bfloat16 *xh, *xl, *ah, *al, *wqh, *wql, *wph, *wpl;
    cudaGetSymbolAddress((void**)&xh,  g_xh);
    cudaGetSymbolAddress((void**)&xl,  g_xl);
    cudaGetSymbolAddress((void**)&ah,  g_ah);
    cudaGetSymbolAddress((void**)&al,  g_al);
    cudaGetSymbolAddress((void**)&wqh, g_wqh);
    cudaGetSymbolAddress((void**)&wql, g_wql);
    cudaGetSymbolAddress((void**)&wph, g_wph);
    cudaGetSymbolAddress((void**)&wpl, g_wpl);

    cudaFuncSetAttribute(gemm3, cudaFuncAttributeMaxDynamicSharedMemorySize, 61440);

    split_x<<<TOTAL * 64 / 256, 256>>>((const float4*)x, lens);
    tsplit2<<<dim3(24, 8, 2), dim3(32, 8)>>>(qkv_w, proj_w);
    gemm3<<<dim3(12, 51), 256, 61440>>>(xh, xl, wqh, wql, qkv_b, nullptr, 1);
    attn4<<<dim3(8, HEADS, BATCH), 256>>>(lens);
    gemm3<<<dim3(4, 51), 256, 61440>>>(ah, al, wph, wpl, proj_b, out, 0);
}

// round 5
// speedup vs baseline: 3.6331x; 1.1333x over previous
#include <cuda_runtime.h>
#include <cuda_bf16.h>
#include <cuda_fp16.h>
#include <cstdint>

#define TOTAL 6464
#define TPAD  6656
#define HEADS 8
#define BATCH 8
#define NPERS 296          // persistent CTAs (148 SMs x 2)

// ---------------- scratch ----------------------------------------------------
__device__ uint32_t g_q16[TPAD * 128];          // fp16x2 [token][128], Q scaled by sc*log2e
__device__ uint32_t g_k16[TPAD * 128];
__device__ __half   g_vt[HEADS * 32 * TPAD];    // V^T: [head][dim][token]
__device__ __nv_bfloat16 g_xh[TPAD * 256], g_xl[TPAD * 256];
__device__ __nv_bfloat16 g_ah[TPAD * 256], g_al[TPAD * 256];
__device__ __nv_bfloat16 g_wqh[768 * 256], g_wql[768 * 256];
__device__ __nv_bfloat16 g_wph[256 * 256], g_wpl[256 * 256];
__device__ int g_off[BATCH + 1];
__device__ int g_pairs[64];
__device__ int g_nwork;
__device__ int g_ticket;

// ---------------- helpers ----------------------------------------------------
__device__ __forceinline__ uint32_t packbf(float x, float y) {
    __nv_bfloat162 t = __floats2bfloat162_rn(x, y);
    return reinterpret_cast<uint32_t&>(t);
}
__device__ __forceinline__ uint32_t packh2(float x, float y) {
    __half2 t = __floats2half2_rn(x, y);
    return reinterpret_cast<uint32_t&>(t);
}
__device__ __forceinline__ float bfhi(float x) {
    return __bfloat162float(__float2bfloat16(x));
}
__device__ __forceinline__ float ex2(float x) {
    float y; asm("ex2.approx.f32 %0, %1;" : "=f"(y) : "f"(x)); return y;
}
__device__ __forceinline__ void mma_bf16(float* c, const uint32_t* a, const uint32_t* b) {
    asm("mma.sync.aligned.m16n8k16.row.col.f32.bf16.bf16.f32 "
        "{%0,%1,%2,%3},{%4,%5,%6,%7},{%8,%9},{%0,%1,%2,%3};"
        : "+f"(c[0]), "+f"(c[1]), "+f"(c[2]), "+f"(c[3])
        : "r"(a[0]), "r"(a[1]), "r"(a[2]), "r"(a[3]), "r"(b[0]), "r"(b[1]));
}
__device__ __forceinline__ void mma_f16(float* c, uint32_t a0, uint32_t a1,
                                        uint32_t a2, uint32_t a3,
                                        uint32_t b0, uint32_t b1) {
    asm("mma.sync.aligned.m16n8k16.row.col.f32.f16.f16.f32 "
        "{%0,%1,%2,%3},{%4,%5,%6,%7},{%8,%9},{%0,%1,%2,%3};"
        : "+f"(c[0]), "+f"(c[1]), "+f"(c[2]), "+f"(c[3])
        : "r"(a0), "r"(a1), "r"(a2), "r"(a3), "r"(b0), "r"(b1));
}
__device__ __forceinline__ void ldm4(uint32_t* d, uint32_t addr) {
    asm volatile("ldmatrix.sync.aligned.m8n8.x4.shared.b16 {%0,%1,%2,%3}, [%4];"
                 : "=r"(d[0]), "=r"(d[1]), "=r"(d[2]), "=r"(d[3]) : "r"(addr));
}
__device__ __forceinline__ void cpa16(void* dst_smem, const void* src) {
    uint32_t d = (uint32_t)__cvta_generic_to_shared(dst_smem);
    asm volatile("cp.async.cg.shared.global [%0], [%1], 16;" :: "r"(d), "l"(src));
}
__device__ __forceinline__ void cpa8(void* dst_smem, const void* src) {
    uint32_t d = (uint32_t)__cvta_generic_to_shared(dst_smem);
    asm volatile("cp.async.ca.shared.global [%0], [%1], 8;" :: "r"(d), "l"(src));
}
#define CP_COMMIT asm volatile("cp.async.commit_group;")
#define CP_WAIT(n) asm volatile("cp.async.wait_group %0;" :: "n"(n))

// ---------------- setup: split x + offsets + work list -----------------------
__global__ void split_x(const float4* __restrict__ x, const int* __restrict__ lens) {
    int i = blockIdx.x * blockDim.x + threadIdx.x;
    if (i == 0) {
        int s = 0;
        for (int k = 0; k < BATCH; k++) { g_off[k] = s; s += lens[k]; }
        g_off[BATCH] = s;
        // work list sorted by length descending
        int ord[BATCH];
        for (int k = 0; k < BATCH; k++) ord[k] = k;
        for (int a = 1; a < BATCH; a++) {
            int key = ord[a], j = a - 1;
            while (j >= 0 && lens[ord[j]] < lens[key]) { ord[j + 1] = ord[j]; j--; }
            ord[j + 1] = key;
        }
        int n = 0;
        for (int a = 0; a < BATCH; a++) {
            int b = ord[a];
            int nt = (lens[b] + 127) >> 7;
            for (int qt = 0; qt < nt; qt++) g_pairs[n++] = (b << 8) | qt;
        }
        g_nwork = n * HEADS;
        g_ticket = 0;
    }
    float4 v = x[i];
    uint32_t* H = (uint32_t*)g_xh;
    uint32_t* L = (uint32_t*)g_xl;
    float hx = bfhi(v.x), hy = bfhi(v.y), hz = bfhi(v.z), hw = bfhi(v.w);
    H[2 * i + 0] = packbf(v.x, v.y);
    H[2 * i + 1] = packbf(v.z, v.w);
    L[2 * i + 0] = packbf(v.x - hx, v.y - hy);
    L[2 * i + 1] = packbf(v.z - hz, v.w - hw);
}

// transpose-split both weights (z=0: qkv N=768, z=1: proj N=256)
__global__ void tsplit2(const float* __restrict__ Wq, const float* __restrict__ Wp) {
    const float* W; __nv_bfloat16 *OH, *OL; int N;
    if (blockIdx.z == 0) { W = Wq; OH = g_wqh; OL = g_wql; N = 768; }
    else                 { W = Wp; OH = g_wph; OL = g_wpl; N = 256;
                           if (blockIdx.x >= 8) return; }
    __shared__ float t[32][33];
    int n0 = blockIdx.x * 32, k0 = blockIdx.y * 32;
    int tx = threadIdx.x, ty = threadIdx.y;
    #pragma unroll
    for (int j = 0; j < 4; j++)
        t[ty + 8 * j][tx] = W[(size_t)(k0 + ty + 8 * j) * N + n0 + tx];
    __syncthreads();
    #pragma unroll
    for (int j = 0; j < 4; j++) {
        float v = t[tx][ty + 8 * j];
        int n = n0 + ty + 8 * j, k = k0 + tx;
        float h = bfhi(v);
        OH[(size_t)n * 256 + k] = __float2bfloat16(v);
        OL[(size_t)n * 256 + k] = __float2bfloat16(v - h);
    }
}

// ---------------------------------------------------------------------------
// GEMM: C = A @ B^T + bias, split-bf16 3-pass, ldmatrix fragment loads.
// Tile 128x64, BK=32, 256 thr, cp.async double-buffered.
// ---------------------------------------------------------------------------
__global__ __launch_bounds__(256, 2) void gemm3(
    const __nv_bfloat16* __restrict__ Ah, const __nv_bfloat16* __restrict__ Al,
    const __nv_bfloat16* __restrict__ Bh, const __nv_bfloat16* __restrict__ Bl,
    const float* __restrict__ bias, float* __restrict__ out, int mode)
{
    extern __shared__ uint32_t sm[];
    uint32_t* AsH = sm;            // [2][128][20] u32
    uint32_t* AsL = sm + 5120;
    uint32_t* BsH = sm + 10240;    // [2][64][20]
    uint32_t* BsL = sm + 12800;

    const int tid = threadIdx.x, lane = tid & 31, wid = tid >> 5;
    const int g = lane >> 2, tig = lane & 3;
    const int wm = (wid >> 1) * 32, wn = (wid & 1) * 32;
    const int row0 = blockIdx.y * 128, col0 = blockIdx.x * 64;
    const int r8 = lane & 7, msel = lane >> 3;

    const uint32_t sbase = (uint32_t)__cvta_generic_to_shared(sm);
    const uint32_t offA = (uint32_t)(((msel & 1) * 8 + r8) * 80 + (msel >> 1) * 16);
    const uint32_t offB = (uint32_t)((msel >> 1) * 640 + r8 * 80 + (msel & 1) * 16);

    float c[2][4][4] = {};

    {
        #pragma unroll
        for (int i = 0; i < 2; i++) {
            int idx = tid + i * 256;
            int r = idx >> 2, s = idx & 3;
            size_t sa = (size_t)(row0 + r) * 256 + s * 8;
            cpa16(&AsH[r * 20 + s * 4], Ah + sa);
            cpa16(&AsL[r * 20 + s * 4], Al + sa);
        }
        int r = tid >> 2, s = tid & 3;
        size_t sb = (size_t)(col0 + r) * 256 + s * 8;
        cpa16(&BsH[r * 20 + s * 4], Bh + sb);
        cpa16(&BsL[r * 20 + s * 4], Bl + sb);
        CP_COMMIT;
    }

    for (int it = 0; it < 8; it++) {
        if (it < 7) {
            int buf = (it + 1) & 1, ko = (it + 1) * 32;
            #pragma unroll
            for (int i = 0; i < 2; i++) {
                int idx = tid + i * 256;
                int r = idx >> 2, s = idx & 3;
                size_t sa = (size_t)(row0 + r) * 256 + ko + s * 8;
                cpa16(&AsH[buf * 2560 + r * 20 + s * 4], Ah + sa);
                cpa16(&AsL[buf * 2560 + r * 20 + s * 4], Al + sa);
            }
            int r = tid >> 2, s = tid & 3;
            size_t sb = (size_t)(col0 + r) * 256 + ko + s * 8;
            cpa16(&BsH[buf * 1280 + r * 20 + s * 4], Bh + sb);
            cpa16(&BsL[buf * 1280 + r * 20 + s * 4], Bl + sb);
            CP_COMMIT;
            CP_WAIT(1);
        } else {
            CP_WAIT(0);
        }
        __syncthreads();

        const int buf = it & 1;
        const uint32_t aBufH = sbase + buf * 10240;
        const uint32_t aBufL = aBufH + 20480;
        const uint32_t bBufH = sbase + 40960 + buf * 5120;
        const uint32_t bBufL = bBufH + 10240;

        #pragma unroll
        for (int ks = 0; ks < 2; ks++) {
            uint32_t ah[2][4], al[2][4], bh[2][4], bl[2][4];
            #pragma unroll
            for (int mt = 0; mt < 2; mt++) {
                uint32_t ao = (uint32_t)((wm + mt * 16) * 80 + ks * 32) + offA;
                ldm4(ah[mt], aBufH + ao);
                ldm4(al[mt], aBufL + ao);
            }
            #pragma unroll
            for (int p = 0; p < 2; p++) {
                uint32_t bo = (uint32_t)(wn * 80 + p * 1280 + ks * 32) + offB;
                ldm4(bh[p], bBufH + bo);
                ldm4(bl[p], bBufL + bo);
            }
            #pragma unroll
            for (int mt = 0; mt < 2; mt++)
                #pragma unroll
                for (int nt = 0; nt < 4; nt++) {
                    const uint32_t* bhp = &bh[nt >> 1][(nt & 1) * 2];
                    const uint32_t* blp = &bl[nt >> 1][(nt & 1) * 2];
                    mma_bf16(c[mt][nt], ah[mt], bhp);
                    mma_bf16(c[mt][nt], ah[mt], blp);
                    mma_bf16(c[mt][nt], al[mt], bhp);
                }
        }
        __syncthreads();
    }

    const float sc = 0.17677669529663687f * 1.4426950408889634f;  // hd^-0.5 * log2(e)
    #pragma unroll
    for (int mt = 0; mt < 2; mt++)
        #pragma unroll
        for (int nt = 0; nt < 4; nt++) {
            int r = row0 + wm + mt * 16 + g;
            int j = col0 + wn + nt * 8 + 2 * tig;
            float2 bv = *(const float2*)&bias[j];
            float v0 = c[mt][nt][0] + bv.x, v1 = c[mt][nt][1] + bv.y;
            float v2 = c[mt][nt][2] + bv.x, v3 = c[mt][nt][3] + bv.y;
            if (mode == 0) {
                if (r < TOTAL) { float2 o = {v0, v1};
                    *(float2*)&out[(size_t)r * 256 + j] = o; }
                if (r + 8 < TOTAL) { float2 o = {v2, v3};
                    *(float2*)&out[(size_t)(r + 8) * 256 + j] = o; }
            } else {
                int arr = j >> 8, jc = j & 255;
                if (arr == 0) {
                    g_q16[(size_t)r * 128 + (jc >> 1)] = packh2(v0 * sc, v1 * sc);
                    g_q16[(size_t)(r + 8) * 128 + (jc >> 1)] = packh2(v2 * sc, v3 * sc);
                } else if (arr == 1) {
                    g_k16[(size_t)r * 128 + (jc >> 1)] = packh2(v0, v1);
                    g_k16[(size_t)(r + 8) * 128 + (jc >> 1)] = packh2(v2, v3);
                } else {
                    int hh = jc >> 5, d = jc & 31;
                    size_t base = (size_t)(hh * 32 + d) * TPAD;
                    g_vt[base + r]            = __float2half(v0);
                    g_vt[base + TPAD + r]     = __float2half(v1);
                    g_vt[base + r + 8]        = __float2half(v2);
                    g_vt[base + TPAD + r + 8] = __float2half(v3);
                }
            }
        }
}

// ---------------------------------------------------------------------------
// Persistent ragged flash attention, fp16 mma, no online softmax (bounded
// log2-domain scores -> direct ex2, single end normalization), ldmatrix
// fragment loads, atomic-ticket work scheduling.
// ---------------------------------------------------------------------------
__global__ __launch_bounds__(256, 2) void attn5(const int* __restrict__ lens)
{
    __shared__ __align__(16) uint32_t Ks[2][64][20];
    __shared__ __align__(16) uint32_t Vt[2][32][36];
    __shared__ int s_w;

    const int tid = threadIdx.x, lane = tid & 31, wid = tid >> 5;
    const int g = lane >> 2, tig = lane & 3;
    const int m0 = wid * 16;
    const uint32_t kbase = (uint32_t)__cvta_generic_to_shared(&Ks[0][0][0]);
    const uint32_t vbase = (uint32_t)__cvta_generic_to_shared(&Vt[0][0][0]);
    const uint32_t laneK = (uint32_t)((lane >> 4) * 640 + (lane & 7) * 80 + ((lane >> 3) & 1) * 16);
    const uint32_t laneV = (uint32_t)((lane >> 4) * 1152 + (lane & 7) * 144 + ((lane >> 3) & 1) * 16);

    for (;;) {
        if (tid == 0) s_w = atomicAdd(&g_ticket, 1);
        __syncthreads();
        const int w = s_w;
        if (w >= g_nwork) return;
        const int pr = g_pairs[w >> 3], h = w & 7;
        const int b = pr >> 8, qt = pr & 255;
        const int L = lens[b], q0 = qt * 128, off = g_off[b];

        // Q fragments (fp16, pre-scaled)
        uint32_t qf[2][4];
        {
            size_t rA = (size_t)(off + q0 + m0 + g) * 128;
            size_t rB = rA + 8 * 128;
            #pragma unroll
            for (int ks = 0; ks < 2; ks++) {
                int cb = h * 16 + ks * 8;
                qf[ks][0] = g_q16[rA + cb + tig];
                qf[ks][1] = g_q16[rB + cb + tig];
                qf[ks][2] = g_q16[rA + cb + tig + 4];
                qf[ks][3] = g_q16[rB + cb + tig + 4];
            }
        }

        float o[4][4];
        #pragma unroll
        for (int nt = 0; nt < 4; nt++)
            #pragma unroll
            for (int i = 0; i < 4; i++) o[nt][i] = 0.f;
        float l0 = 0.f, l1 = 0.f;

        const int nch = (L + 63) >> 6;

        #pragma unroll
        for (int i = 0; i < 3; i++) {
            int idx = tid + i * 256;
            if (idx < 256) {
                int r = idx >> 2, s = idx & 3;
                cpa16(&Ks[0][r][s * 4], g_k16 + (size_t)(off + r) * 128 + h * 16 + s * 4);
            } else {
                int j = idx - 256;
                int d = j >> 4, s = j & 15;
                cpa8(&Vt[0][d][s * 2], g_vt + (size_t)(h * 32 + d) * TPAD + off + s * 4);
            }
        }
        CP_COMMIT;

        for (int c = 0; c < nch; c++) {
            if (c + 1 < nch) {
                int buf = (c + 1) & 1, k0n = (c + 1) * 64;
                #pragma unroll
                for (int i = 0; i < 3; i++) {
                    int idx = tid + i * 256;
                    if (idx < 256) {
                        int r = idx >> 2, s = idx & 3;
                        cpa16(&Ks[buf][r][s * 4],
                              g_k16 + (size_t)(off + k0n + r) * 128 + h * 16 + s * 4);
                    } else {
                        int j = idx - 256;
                        int d = j >> 4, s = j & 15;
                        cpa8(&Vt[buf][d][s * 2],
                             g_vt + (size_t)(h * 32 + d) * TPAD + off + k0n + s * 4);
                    }
                }
                CP_COMMIT;
                CP_WAIT(1);
            } else {
                CP_WAIT(0);
            }
            __syncthreads();

            const int buf = c & 1;
            const int k0 = c * 64;

            // S = Q @ K^T (log2 domain)
            float s_[8][4] = {};
            const uint32_t kb = kbase + buf * 5120;
            #pragma unroll
            for (int ks = 0; ks < 2; ks++) {
                #pragma unroll
                for (int p = 0; p < 4; p++) {
                    uint32_t kr[4];
                    ldm4(kr, kb + p * 1280 + ks * 32 + laneK);
                    mma_f16(s_[2 * p], qf[ks][0], qf[ks][1], qf[ks][2], qf[ks][3],
                            kr[0], kr[1]);
                    mma_f16(s_[2 * p + 1], qf[ks][0], qf[ks][1], qf[ks][2], qf[ks][3],
                            kr[2], kr[3]);
                }
            }
            // ragged key mask (last partial chunk only)
            if (k0 + 64 > L) {
                #pragma unroll
                for (int jt = 0; jt < 8; jt++) {
                    int col = k0 + jt * 8 + 2 * tig;
                    if (col >= L)     { s_[jt][0] = -1e9f; s_[jt][2] = -1e9f; }
                    if (col + 1 >= L) { s_[jt][1] = -1e9f; s_[jt][3] = -1e9f; }
                }
            }
            // p = exp2(s), accumulate row sums (no max subtraction)
            float ps0 = 0.f, ps1 = 0.f;
            #pragma unroll
            for (int jt = 0; jt < 8; jt++) {
                s_[jt][0] = ex2(s_[jt][0]); ps0 += s_[jt][0];
                s_[jt][1] = ex2(s_[jt][1]); ps0 += s_[jt][1];
                s_[jt][2] = ex2(s_[jt][2]); ps1 += s_[jt][2];
                s_[jt][3] = ex2(s_[jt][3]); ps1 += s_[jt][3];
            }
            l0 += ps0; l1 += ps1;

            // O += P @ V (P fragments = direct packs of S accumulators)
            const uint32_t vb = vbase + buf * 4608;
            #pragma unroll
            for (int t = 0; t < 4; t++) {
                uint32_t a0 = packh2(s_[2 * t][0],     s_[2 * t][1]);
                uint32_t a1 = packh2(s_[2 * t][2],     s_[2 * t][3]);
                uint32_t a2 = packh2(s_[2 * t + 1][0], s_[2 * t + 1][1]);
                uint32_t a3 = packh2(s_[2 * t + 1][2], s_[2 * t + 1][3]);
                #pragma unroll
                for (int q = 0; q < 2; q++) {
                    uint32_t vr[4];
                    ldm4(vr, vb + q * 2304 + t * 32 + laneV);
                    mma_f16(o[2 * q],     a0, a1, a2, a3, vr[0], vr[1]);
                    mma_f16(o[2 * q + 1], a0, a1, a2, a3, vr[2], vr[3]);
                }
            }
            __syncthreads();
        }

        l0 += __shfl_xor_sync(0xffffffffu, l0, 1);
        l0 += __shfl_xor_sync(0xffffffffu, l0, 2);
        l1 += __shfl_xor_sync(0xffffffffu, l1, 1);
        l1 += __shfl_xor_sync(0xffffffffu, l1, 2);
        float i0 = 1.f / l0, i1 = 1.f / l1;

        int qa = q0 + m0 + g, qb = qa + 8;
        uint32_t* AH = (uint32_t*)g_ah;
        uint32_t* AL = (uint32_t*)g_al;
        #pragma unroll
        for (int nt = 0; nt < 4; nt++) {
            int ci = h * 16 + nt * 4 + tig;
            if (qa < L) {
                float v0 = o[nt][0] * i0, v1 = o[nt][1] * i0;
                float h0 = bfhi(v0), h1 = bfhi(v1);
                AH[(size_t)(off + qa) * 128 + ci] = packbf(v0, v1);
                AL[(size_t)(off + qa) * 128 + ci] = packbf(v0 - h0, v1 - h1);
            }
            if (qb < L) {
                float v2 = o[nt][2] * i1, v3 = o[nt][3] * i1;
                float h2 = bfhi(v2), h3 = bfhi(v3);
                AH[(size_t)(off + qb) * 128 + ci] = packbf(v2, v3);
                AL[(size_t)(off + qb) * 128 + ci] = packbf(v2 - h2, v3 - h3);
            }
        }
    }
}

// ---------------------------------------------------------------------------
extern "C" void kernel_launch(void* const* d_in, const int* in_sizes, int n_in,
                              void* d_out, int out_size)
{
    const float* x      = (const float*)d_in[0];
    const int*   lens   = (const int*)d_in[2];
    const float* qkv_w  = (const float*)d_in[3];
    const float* qkv_b  = (const float*)d_in[4];
    const float* proj_w = (const float*)d_in[5];
    const float* proj_b = (const float*)d_in[6];
    float* out = (float*)d_out;

    __nv_bfloat16 *xh, *xl, *ah, *al, *wqh, *wql, *wph, *wpl;
    cudaGetSymbolAddress((void**)&xh,  g_xh);
    cudaGetSymbolAddress((void**)&xl,  g_xl);
    cudaGetSymbolAddress((void**)&ah,  g_ah);
    cudaGetSymbolAddress((void**)&al,  g_al);
    cudaGetSymbolAddress((void**)&wqh, g_wqh);
    cudaGetSymbolAddress((void**)&wql, g_wql);
    cudaGetSymbolAddress((void**)&wph, g_wph);
    cudaGetSymbolAddress((void**)&wpl, g_wpl);

    cudaFuncSetAttribute(gemm3, cudaFuncAttributeMaxDynamicSharedMemorySize, 61440);

    split_x<<<TOTAL * 64 / 256, 256>>>((const float4*)x, lens);
    tsplit2<<<dim3(24, 8, 2), dim3(32, 8)>>>(qkv_w, proj_w);
    gemm3<<<dim3(12, 51), 256, 61440>>>(xh, xl, wqh, wql, qkv_b, nullptr, 1);
    attn5<<<NPERS, 256>>>(lens);
    gemm3<<<dim3(4, 51), 256, 61440>>>(ah, al, wph, wpl, proj_b, out, 0);
}

// round 6
// speedup vs baseline: 4.2806x; 1.1782x over previous
#include <cuda_runtime.h>
#include <cuda_bf16.h>
#include <cuda_fp16.h>
#include <cstdint>

#define TOTAL 6464
#define TPAD  6656
#define HEADS 8
#define BATCH 8
#define NPERS 296

// ---------------- scratch ----------------------------------------------------
__device__ uint32_t g_q16[TPAD * 128];   // fp16x2 [token][128], Q scaled by sc*log2e
__device__ uint32_t g_k16[TPAD * 128];
__device__ uint32_t g_v16[TPAD * 128];   // V row-major fp16x2 (same layout as K)
__device__ __nv_bfloat16 g_xh[TPAD * 256], g_xl[TPAD * 256];
__device__ __nv_bfloat16 g_ah[TPAD * 256], g_al[TPAD * 256];
__device__ __nv_bfloat16 g_wqh[768 * 256], g_wql[768 * 256];
__device__ __nv_bfloat16 g_wph[256 * 256], g_wpl[256 * 256];
__device__ int g_off[BATCH + 1];
__device__ int g_pairs[64];
__device__ int g_nwork;
__device__ int g_ticket;

// ---------------- helpers ----------------------------------------------------
__device__ __forceinline__ uint32_t packbf(float x, float y) {
    __nv_bfloat162 t = __floats2bfloat162_rn(x, y);
    return reinterpret_cast<uint32_t&>(t);
}
__device__ __forceinline__ uint32_t packh2(float x, float y) {
    __half2 t = __floats2half2_rn(x, y);
    return reinterpret_cast<uint32_t&>(t);
}
__device__ __forceinline__ float bfhi(float x) {
    return __bfloat162float(__float2bfloat16(x));
}
__device__ __forceinline__ uint32_t ex2h2(uint32_t x) {
    uint32_t y; asm("ex2.approx.f16x2 %0, %1;" : "=r"(y) : "r"(x)); return y;
}
__device__ __forceinline__ void mma_bf16(float* c, const uint32_t* a, const uint32_t* b) {
    asm("mma.sync.aligned.m16n8k16.row.col.f32.bf16.bf16.f32 "
        "{%0,%1,%2,%3},{%4,%5,%6,%7},{%8,%9},{%0,%1,%2,%3};"
        : "+f"(c[0]), "+f"(c[1]), "+f"(c[2]), "+f"(c[3])
        : "r"(a[0]), "r"(a[1]), "r"(a[2]), "r"(a[3]), "r"(b[0]), "r"(b[1]));
}
__device__ __forceinline__ void mma_f16(float* c, uint32_t a0, uint32_t a1,
                                        uint32_t a2, uint32_t a3,
                                        uint32_t b0, uint32_t b1) {
    asm("mma.sync.aligned.m16n8k16.row.col.f32.f16.f16.f32 "
        "{%0,%1,%2,%3},{%4,%5,%6,%7},{%8,%9},{%0,%1,%2,%3};"
        : "+f"(c[0]), "+f"(c[1]), "+f"(c[2]), "+f"(c[3])
        : "r"(a0), "r"(a1), "r"(a2), "r"(a3), "r"(b0), "r"(b1));
}
__device__ __forceinline__ void ldm4(uint32_t* d, uint32_t addr) {
    asm volatile("ldmatrix.sync.aligned.m8n8.x4.shared.b16 {%0,%1,%2,%3}, [%4];"
                 : "=r"(d[0]), "=r"(d[1]), "=r"(d[2]), "=r"(d[3]) : "r"(addr));
}
__device__ __forceinline__ void ldm4t(uint32_t* d, uint32_t addr) {
    asm volatile("ldmatrix.sync.aligned.m8n8.x4.trans.shared.b16 {%0,%1,%2,%3}, [%4];"
                 : "=r"(d[0]), "=r"(d[1]), "=r"(d[2]), "=r"(d[3]) : "r"(addr));
}
__device__ __forceinline__ void cpa16(uint32_t dst_smem, const void* src) {
    asm volatile("cp.async.cg.shared.global [%0], [%1], 16;" :: "r"(dst_smem), "l"(src));
}
#define CP_COMMIT asm volatile("cp.async.commit_group;")
#define CP_WAIT0 asm volatile("cp.async.wait_group 0;")

// ---------------- fused prep: split x, offsets, work list, weight transposes -
__global__ void prep(const float4* __restrict__ x, const int* __restrict__ lens,
                     const float* __restrict__ Wq, const float* __restrict__ Wp)
{
    const int blk = blockIdx.x, tid = threadIdx.x;
    if (blk < 1616) {
        int i = blk * 256 + tid;
        if (i == 0) {
            int s = 0;
            for (int k = 0; k < BATCH; k++) { g_off[k] = s; s += lens[k]; }
            g_off[BATCH] = s;
            int ord[BATCH];
            for (int k = 0; k < BATCH; k++) ord[k] = k;
            for (int a = 1; a < BATCH; a++) {
                int key = ord[a], j = a - 1;
                while (j >= 0 && lens[ord[j]] < lens[key]) { ord[j + 1] = ord[j]; j--; }
                ord[j + 1] = key;
            }
            int n = 0;
            for (int a = 0; a < BATCH; a++) {
                int b = ord[a];
                int nt = (lens[b] + 127) >> 7;
                for (int qt = 0; qt < nt; qt++) g_pairs[n++] = (b << 8) | qt;
            }
            g_nwork = n * HEADS;
            g_ticket = 0;
        }
        float4 v = x[i];
        uint32_t* H = (uint32_t*)g_xh;
        uint32_t* L = (uint32_t*)g_xl;
        float hx = bfhi(v.x), hy = bfhi(v.y), hz = bfhi(v.z), hw = bfhi(v.w);
        H[2 * i + 0] = packbf(v.x, v.y);
        H[2 * i + 1] = packbf(v.z, v.w);
        L[2 * i + 0] = packbf(v.x - hx, v.y - hy);
        L[2 * i + 1] = packbf(v.z - hz, v.w - hw);
        return;
    }
    // weight transpose-split
    const float* W; __nv_bfloat16 *OH, *OL; int N, n0, k0;
    if (blk < 1808) {
        int idx = blk - 1616;
        W = Wq; OH = g_wqh; OL = g_wql; N = 768;
        n0 = (idx % 24) * 32; k0 = (idx / 24) * 32;
    } else {
        int idx = blk - 1808;
        W = Wp; OH = g_wph; OL = g_wpl; N = 256;
        n0 = (idx % 8) * 32; k0 = (idx / 8) * 32;
    }
    __shared__ float t[32][33];
    int tx = tid & 31, ty = tid >> 5;
    #pragma unroll
    for (int j = 0; j < 4; j++)
        t[ty + 8 * j][tx] = W[(size_t)(k0 + ty + 8 * j) * N + n0 + tx];
    __syncthreads();
    #pragma unroll
    for (int j = 0; j < 4; j++) {
        float v = t[tx][ty + 8 * j];
        int n = n0 + ty + 8 * j, k = k0 + tx;
        float h = bfhi(v);
        OH[(size_t)n * 256 + k] = __float2bfloat16(v);
        OL[(size_t)n * 256 + k] = __float2bfloat16(v - h);
    }
}

// ---------------------------------------------------------------------------
// GEMM: C = A @ B^T + bias, split-bf16 3-pass with split accumulators,
// ldmatrix fragment loads, 1 sync per K-iter. Tile 128x64, BK=32, 256 thr.
// mode 0: fp32 out. mode 1: QKV epilogue -> g_q16/g_k16/g_v16 (fp16x2).
// ---------------------------------------------------------------------------
__global__ __launch_bounds__(256, 2) void gemm3(
    const __nv_bfloat16* __restrict__ Ah, const __nv_bfloat16* __restrict__ Al,
    const __nv_bfloat16* __restrict__ Bh, const __nv_bfloat16* __restrict__ Bl,
    const float* __restrict__ bias, float* __restrict__ out, int mode)
{
    extern __shared__ uint32_t sm[];
    uint32_t* AsH = sm;            // [2][128][20] u32
    uint32_t* AsL = sm + 5120;
    uint32_t* BsH = sm + 10240;    // [2][64][20]
    uint32_t* BsL = sm + 12800;

    const int tid = threadIdx.x, lane = tid & 31, wid = tid >> 5;
    const int g = lane >> 2, tig = lane & 3;
    const int wm = (wid >> 1) * 32, wn = (wid & 1) * 32;
    const int row0 = blockIdx.y * 128, col0 = blockIdx.x * 64;
    const int r8 = lane & 7, msel = lane >> 3;

    const uint32_t sbase = (uint32_t)__cvta_generic_to_shared(sm);
    const uint32_t offA = (uint32_t)(((msel & 1) * 8 + r8) * 80 + (msel >> 1) * 16);
    const uint32_t offB = (uint32_t)((msel >> 1) * 640 + r8 * 80 + (msel & 1) * 16);

    // loop-carried staging pointers
    const int ra = tid >> 2, sa = tid & 3;
    const __nv_bfloat16* pAh = Ah + (size_t)(row0 + ra) * 256 + sa * 8;
    const __nv_bfloat16* pAl = Al + (size_t)(row0 + ra) * 256 + sa * 8;
    const __nv_bfloat16* pAh2 = pAh + 64 * 256;
    const __nv_bfloat16* pAl2 = pAl + 64 * 256;
    const __nv_bfloat16* pBh = Bh + (size_t)(col0 + ra) * 256 + sa * 8;
    const __nv_bfloat16* pBl = Bl + (size_t)(col0 + ra) * 256 + sa * 8;
    const uint32_t dA = sbase + (uint32_t)(ra * 80 + sa * 16);
    const uint32_t dB = sbase + 40960 + (uint32_t)(ra * 80 + sa * 16);

    float chi[2][4][4] = {};
    float clo[2][4][4] = {};

    // stage 0
    cpa16(dA, pAh);            cpa16(dA + 20480, pAl);
    cpa16(dA + 5120, pAh2);    cpa16(dA + 25600, pAl2);
    cpa16(dB, pBh);            cpa16(dB + 10240, pBl);
    CP_COMMIT;
    pAh += 32; pAl += 32; pAh2 += 32; pAl2 += 32; pBh += 32; pBl += 32;

    for (int it = 0; it < 8; it++) {
        CP_WAIT0;
        __syncthreads();
        if (it < 7) {
            uint32_t bo = ((it + 1) & 1) ? 10240u : 0u;
            uint32_t bo2 = ((it + 1) & 1) ? 5120u : 0u;
            cpa16(dA + bo, pAh);          cpa16(dA + 20480 + bo, pAl);
            cpa16(dA + 5120 + bo, pAh2);  cpa16(dA + 25600 + bo, pAl2);
            cpa16(dB + bo2, pBh);         cpa16(dB + 10240 + bo2, pBl);
            CP_COMMIT;
            pAh += 32; pAl += 32; pAh2 += 32; pAl2 += 32; pBh += 32; pBl += 32;
        }

        const int buf = it & 1;
        const uint32_t aBufH = sbase + buf * 10240;
        const uint32_t aBufL = aBufH + 20480;
        const uint32_t bBufH = sbase + 40960 + buf * 5120;
        const uint32_t bBufL = bBufH + 10240;

        #pragma unroll
        for (int ks = 0; ks < 2; ks++) {
            uint32_t ah[2][4], al[2][4], bh[2][4], bl[2][4];
            #pragma unroll
            for (int mt = 0; mt < 2; mt++) {
                uint32_t ao = (uint32_t)((wm + mt * 16) * 80 + ks * 32) + offA;
                ldm4(ah[mt], aBufH + ao);
                ldm4(al[mt], aBufL + ao);
            }
            #pragma unroll
            for (int p = 0; p < 2; p++) {
                uint32_t bo = (uint32_t)(wn * 80 + p * 1280 + ks * 32) + offB;
                ldm4(bh[p], bBufH + bo);
                ldm4(bl[p], bBufL + bo);
            }
            #pragma unroll
            for (int mt = 0; mt < 2; mt++)
                #pragma unroll
                for (int nt = 0; nt < 4; nt++) {
                    const uint32_t* bhp = &bh[nt >> 1][(nt & 1) * 2];
                    const uint32_t* blp = &bl[nt >> 1][(nt & 1) * 2];
                    mma_bf16(chi[mt][nt], ah[mt], bhp);
                    mma_bf16(clo[mt][nt], ah[mt], blp);
                    mma_bf16(clo[mt][nt], al[mt], bhp);
                }
        }
        __syncthreads();
    }

    const float sc = 0.17677669529663687f * 1.4426950408889634f;
    #pragma unroll
    for (int mt = 0; mt < 2; mt++)
        #pragma unroll
        for (int nt = 0; nt < 4; nt++) {
            int r = row0 + wm + mt * 16 + g;
            int j = col0 + wn + nt * 8 + 2 * tig;
            float2 bv = *(const float2*)&bias[j];
            float v0 = chi[mt][nt][0] + clo[mt][nt][0] + bv.x;
            float v1 = chi[mt][nt][1] + clo[mt][nt][1] + bv.y;
            float v2 = chi[mt][nt][2] + clo[mt][nt][2] + bv.x;
            float v3 = chi[mt][nt][3] + clo[mt][nt][3] + bv.y;
            if (mode == 0) {
                if (r < TOTAL) { float2 o = {v0, v1};
                    *(float2*)&out[(size_t)r * 256 + j] = o; }
                if (r + 8 < TOTAL) { float2 o = {v2, v3};
                    *(float2*)&out[(size_t)(r + 8) * 256 + j] = o; }
            } else {
                int arr = j >> 8, jc = j & 255;
                uint32_t* dst = (arr == 0) ? g_q16 : (arr == 1) ? g_k16 : g_v16;
                float s = (arr == 0) ? sc : 1.f;
                dst[(size_t)r * 128 + (jc >> 1)] = packh2(v0 * s, v1 * s);
                dst[(size_t)(r + 8) * 128 + (jc >> 1)] = packh2(v2 * s, v3 * s);
            }
        }
}

// ---------------------------------------------------------------------------
// Persistent ragged flash attention. fp16 mma; half2 ex2 softmax; row sums via
// an extra all-ones mma (f32, consistent with PV); ldmatrix(.trans) fragments;
// loop-carried cp.async staging; 1 sync per chunk.
// ---------------------------------------------------------------------------
__global__ __launch_bounds__(256, 2) void attn6(const int* __restrict__ lens)
{
    __shared__ __align__(16) uint32_t Ks[2][64][20];
    __shared__ __align__(16) uint32_t Vs[2][64][20];
    __shared__ int s_w;

    const int tid = threadIdx.x, lane = tid & 31, wid = tid >> 5;
    const int g = lane >> 2, tig = lane & 3;
    const int m0 = wid * 16;
    const uint32_t kbase = (uint32_t)__cvta_generic_to_shared(&Ks[0][0][0]);
    const uint32_t vbase = (uint32_t)__cvta_generic_to_shared(&Vs[0][0][0]);
    const uint32_t laneK = (uint32_t)((lane >> 4) * 640 + (lane & 7) * 80 + ((lane >> 3) & 1) * 16);
    const uint32_t laneVt = (uint32_t)(((lane >> 3) & 1) * 640 + (lane & 7) * 80 + (lane >> 4) * 16);
    const int ra = tid >> 2, sa = tid & 3;
    const uint32_t dK = kbase + (uint32_t)(ra * 80 + sa * 16);
    const uint32_t dV = vbase + (uint32_t)(ra * 80 + sa * 16);
    const uint32_t ONE2 = 0x3C003C00u;   // half2(1,1)

    for (;;) {
        if (tid == 0) s_w = atomicAdd(&g_ticket, 1);
        __syncthreads();
        const int w = s_w;
        if (w >= g_nwork) return;
        const int pr = g_pairs[w >> 3], h = w & 7;
        const int b = pr >> 8, qt = pr & 255;
        const int L = lens[b], q0 = qt * 128, off = g_off[b];

        uint32_t qf[2][4];
        {
            size_t rA = (size_t)(off + q0 + m0 + g) * 128;
            size_t rB = rA + 8 * 128;
            #pragma unroll
            for (int ks = 0; ks < 2; ks++) {
                int cb = h * 16 + ks * 8;
                qf[ks][0] = g_q16[rA + cb + tig];
                qf[ks][1] = g_q16[rB + cb + tig];
                qf[ks][2] = g_q16[rA + cb + tig + 4];
                qf[ks][3] = g_q16[rB + cb + tig + 4];
            }
        }

        float o[4][4];
        #pragma unroll
        for (int nt = 0; nt < 4; nt++)
            #pragma unroll
            for (int i = 0; i < 4; i++) o[nt][i] = 0.f;
        float lacc[4] = {0.f, 0.f, 0.f, 0.f};

        const int nch = (L + 63) >> 6;

        // loop-carried staging pointers
        const uint32_t* pk = g_k16 + (size_t)(off + ra) * 128 + h * 16 + sa * 4;
        const uint32_t* pv = g_v16 + (size_t)(off + ra) * 128 + h * 16 + sa * 4;

        cpa16(dK, pk); cpa16(dV, pv);
        CP_COMMIT;
        pk += 64 * 128; pv += 64 * 128;

        for (int c = 0; c < nch; c++) {
            CP_WAIT0;
            __syncthreads();
            if (c + 1 < nch) {
                uint32_t bo = ((c + 1) & 1) ? 5120u : 0u;
                cpa16(dK + bo, pk); cpa16(dV + bo, pv);
                CP_COMMIT;
                pk += 64 * 128; pv += 64 * 128;
            }

            const int buf = c & 1;
            const int k0 = c * 64;

            // S = Q @ K^T (log2 domain)
            float s_[8][4] = {};
            const uint32_t kb = kbase + buf * 5120;
            #pragma unroll
            for (int ks = 0; ks < 2; ks++) {
                #pragma unroll
                for (int p = 0; p < 4; p++) {
                    uint32_t kr[4];
                    ldm4(kr, kb + p * 1280 + ks * 32 + laneK);
                    mma_f16(s_[2 * p], qf[ks][0], qf[ks][1], qf[ks][2], qf[ks][3],
                            kr[0], kr[1]);
                    mma_f16(s_[2 * p + 1], qf[ks][0], qf[ks][1], qf[ks][2], qf[ks][3],
                            kr[2], kr[3]);
                }
            }
            // ragged key mask (last partial chunk only)
            if (k0 + 64 > L) {
                #pragma unroll
                for (int jt = 0; jt < 8; jt++) {
                    int col = k0 + jt * 8 + 2 * tig;
                    if (col >= L)     { s_[jt][0] = -1e9f; s_[jt][2] = -1e9f; }
                    if (col + 1 >= L) { s_[jt][1] = -1e9f; s_[jt][3] = -1e9f; }
                }
            }

            // P = exp2(S) in half2 + PV mma + ones-column row sums
            const uint32_t vb = vbase + buf * 5120;
            #pragma unroll
            for (int t = 0; t < 4; t++) {
                uint32_t a0 = ex2h2(packh2(s_[2 * t][0],     s_[2 * t][1]));
                uint32_t a1 = ex2h2(packh2(s_[2 * t][2],     s_[2 * t][3]));
                uint32_t a2 = ex2h2(packh2(s_[2 * t + 1][0], s_[2 * t + 1][1]));
                uint32_t a3 = ex2h2(packh2(s_[2 * t + 1][2], s_[2 * t + 1][3]));
                uint32_t v0[4], v1[4];
                ldm4t(v0, vb + t * 1280 + laneVt);
                ldm4t(v1, vb + t * 1280 + 32 + laneVt);
                mma_f16(o[0], a0, a1, a2, a3, v0[0], v0[1]);
                mma_f16(o[1], a0, a1, a2, a3, v0[2], v0[3]);
                mma_f16(o[2], a0, a1, a2, a3, v1[0], v1[1]);
                mma_f16(o[3], a0, a1, a2, a3, v1[2], v1[3]);
                mma_f16(lacc, a0, a1, a2, a3, ONE2, ONE2);
            }
            __syncthreads();
        }

        float i0 = 1.f / lacc[0], i1 = 1.f / lacc[2];

        int qa = q0 + m0 + g, qb = qa + 8;
        uint32_t* AH = (uint32_t*)g_ah;
        uint32_t* AL = (uint32_t*)g_al;
        #pragma unroll
        for (int nt = 0; nt < 4; nt++) {
            int ci = h * 16 + nt * 4 + tig;
            if (qa < L) {
                float v0 = o[nt][0] * i0, v1 = o[nt][1] * i0;
                float h0 = bfhi(v0), h1 = bfhi(v1);
                AH[(size_t)(off + qa) * 128 + ci] = packbf(v0, v1);
                AL[(size_t)(off + qa) * 128 + ci] = packbf(v0 - h0, v1 - h1);
            }
            if (qb < L) {
                float v2 = o[nt][2] * i1, v3 = o[nt][3] * i1;
                float h2 = bfhi(v2), h3 = bfhi(v3);
                AH[(size_t)(off + qb) * 128 + ci] = packbf(v2, v3);
                AL[(size_t)(off + qb) * 128 + ci] = packbf(v2 - h2, v3 - h3);
            }
        }
    }
}

// ---------------------------------------------------------------------------
extern "C" void kernel_launch(void* const* d_in, const int* in_sizes, int n_in,
                              void* d_out, int out_size)
{
    const float* x      = (const float*)d_in[0];
    const int*   lens   = (const int*)d_in[2];
    const float* qkv_w  = (const float*)d_in[3];
    const float* qkv_b  = (const float*)d_in[4];
    const float* proj_w = (const float*)d_in[5];
    const float* proj_b = (const float*)d_in[6];
    float* out = (float*)d_out;

    __nv_bfloat16 *xh, *xl, *ah, *al, *wqh, *wql, *wph, *wpl;
    cudaGetSymbolAddress((void**)&xh,  g_xh);
    cudaGetSymbolAddress((void**)&xl,  g_xl);
    cudaGetSymbolAddress((void**)&ah,  g_ah);
    cudaGetSymbolAddress((void**)&al,  g_al);
    cudaGetSymbolAddress((void**)&wqh, g_wqh);
    cudaGetSymbolAddress((void**)&wql, g_wql);
    cudaGetSymbolAddress((void**)&wph, g_wph);
    cudaGetSymbolAddress((void**)&wpl, g_wpl);

    cudaFuncSetAttribute(gemm3, cudaFuncAttributeMaxDynamicSharedMemorySize, 61440);

    prep<<<1872, 256>>>((const float4*)x, lens, qkv_w, proj_w);
    gemm3<<<dim3(12, 51), 256, 61440>>>(xh, xl, wqh, wql, qkv_b, nullptr, 1);
    attn6<<<NPERS, 256>>>(lens);
    gemm3<<<dim3(4, 51), 256, 61440>>>(ah, al, wph, wpl, proj_b, out, 0);
}